// round 2
// baseline (speedup 1.0000x reference)
#include <cuda_runtime.h>
#include <cstdint>

#define BB   128
#define TT   1024
#define HH   512
#define IIN  17
#define OOUT 17
#define NBLK 128
#define NTHR 256

typedef unsigned long long u64;

// ---------------- device scratch ----------------
// h and y0 stored TRANSPOSED: [j][b] so GEMM A-staging is coalesced.
__device__ float g_h0T[2][HH * BB];
__device__ float g_h1T[2][HH * BB];
__device__ float g_y0T[(size_t)TT * HH * BB];   // 256MB, [t][j][b]

__device__ unsigned          g_bar_cnt = 0;
__device__ volatile unsigned g_bar_sense = 0;

// ---------------- grid-wide spin barrier (sense reversing) ----------------
__device__ __forceinline__ void grid_barrier(unsigned* lsense)
{
    __syncthreads();
    if (threadIdx.x == 0) {
        unsigned s = *lsense ^ 1u;
        *lsense = s;
        __threadfence();
        unsigned prev = atomicAdd(&g_bar_cnt, 1u);
        if (prev == NBLK - 1u) {
            atomicExch(&g_bar_cnt, 0u);
            __threadfence();
            g_bar_sense = s;
        } else {
            while (g_bar_sense != s) { }
        }
        __threadfence();
    }
    __syncthreads();
}

// ---------------- packed f32x2 helpers ----------------
__device__ __forceinline__ u64 ffma2(u64 a, u64 b, u64 c) {
    u64 d;
    asm("fma.rn.f32x2 %0, %1, %2, %3;" : "=l"(d) : "l"(a), "l"(b), "l"(c));
    return d;
}
__device__ __forceinline__ u64 pack2(float x, float y) {
    u64 r; asm("mov.b64 %0, {%1, %2};" : "=l"(r) : "f"(x), "f"(y)); return r;
}
__device__ __forceinline__ float2 unpack2(u64 v) {
    float2 f; asm("mov.b64 {%0, %1}, %2;" : "=f"(f.x), "=f"(f.y) : "l"(v)); return f;
}
__device__ __forceinline__ float sigf(float v) { return 1.f / (1.f + expf(-v)); }

// ---------------- A staging: global [k][BB] fp32 -> smem [kk][32] dup'd pairs ----
// smem slot index: kk*32 + (b&15)*2 + (b>>4)  (pairs batches b and b+16 adjacently)
template<int KC, bool LDCG>
__device__ __forceinline__ void stage_A(u64* __restrict__ As,
                                        const float* __restrict__ src,
                                        int k0, int b0, int tid)
{
#pragma unroll
    for (int u = 0; u < (KC * 8) / NTHR; ++u) {
        int idx = tid + u * NTHR;
        int kk = idx >> 3, q = idx & 7;
        const float4* p = (const float4*)(src + (size_t)(k0 + kk) * BB + b0) + q;
        float4 v = LDCG ? __ldcg(p) : *p;
        int b = q * 4;
        int base = kk * 32 + (b & 15) * 2 + (b >> 4);
        As[base + 0] = pack2(v.x, v.x);
        As[base + 2] = pack2(v.y, v.y);
        As[base + 4] = pack2(v.z, v.z);
        As[base + 6] = pack2(v.w, v.w);
    }
}

// ---------------- FFMA2 GEMM chunk ----------------
// As: [kk][32] dup'd h pairs; W: [kk][32] gate-pair weights.
// Thread owns cell tj (gate pairs 2tj,2tj+1) x batches (tb, tb+16).
template<int KC>
__device__ __forceinline__ void compute_chunk(const u64* __restrict__ As,
                                              const u64* __restrict__ W,
                                              int tb, int tj,
                                              u64& a00, u64& a01, u64& a10, u64& a11)
{
#pragma unroll 8
    for (int kk = 0; kk < KC; ++kk) {
        ulonglong2 av = *(const ulonglong2*)(As + kk * 32 + tb * 2);
        ulonglong2 wv = *(const ulonglong2*)(W  + kk * 32 + tj * 2);
        a00 = ffma2(av.x, wv.x, a00);
        a01 = ffma2(av.x, wv.y, a01);
        a10 = ffma2(av.y, wv.x, a10);
        a11 = ffma2(av.y, wv.y, a11);
    }
}

// ---------------- persistent weight pack: W[2048,512] -> smem [k][32] gate pairs
__device__ __forceinline__ void load_Wpers(u64* __restrict__ Wp,
                                           const float* __restrict__ w,
                                           int j0, int tid)
{
    for (int idx = tid; idx < HH * 32; idx += NTHR) {
        int k = idx >> 5, gp = idx & 31;
        int r0 = gp * 2, r1 = r0 + 1;
        int row0 = (r0 & 3) * HH + j0 + (r0 >> 2);
        int row1 = (r1 & 3) * HH + j0 + (r1 >> 2);
        Wp[(size_t)k * 32 + gp] = pack2(w[(size_t)row0 * HH + k],
                                        w[(size_t)row1 * HH + k]);
    }
}

// ================= Layer 0 =================
// smem: Wp[512*32]u64=128KB | As[256*32]u64=64KB | Wi[64*17]f | Xs[32*17]f | cb[64]f
#define SM0_BYTES ((16384 + 8192) * 8 + (1088 + 544 + 64) * 4)

extern "C" __global__ void __launch_bounds__(NTHR, 1)
lstm_l0(const float* __restrict__ x,
        const float* __restrict__ wih, const float* __restrict__ whh,
        const float* __restrict__ bih, const float* __restrict__ bhh)
{
    extern __shared__ u64 sm0[];
    u64*   Wp = sm0;                         // 16384 u64
    u64*   As = sm0 + 16384;                 // 8192 u64
    float* Wi = (float*)(sm0 + 16384 + 8192);
    float* Xs = Wi + 64 * IIN;
    float* cb = Xs + 32 * IIN;

    const int tid = threadIdx.x;
    const int tb = tid & 15, tj = tid >> 4;
    const int b0 = (blockIdx.x >> 5) * 32;
    const int j0 = (blockIdx.x & 31) * 16;

    load_Wpers(Wp, whh, j0, tid);
    for (int idx = tid; idx < 64 * IIN; idx += NTHR) {
        int r = idx / IIN, k = idx - r * IIN;
        Wi[idx] = wih[(size_t)((r & 3) * HH + j0 + (r >> 2)) * IIN + k];
    }
    if (tid < 64) {
        int row = (tid & 3) * HH + j0 + (tid >> 2);
        cb[tid] = bih[row] + bhh[row];
    }
    for (int idx = tid; idx < 16 * 32; idx += NTHR) {
        int jj = idx >> 5, b = idx & 31;
        __stcg(&g_h0T[0][(j0 + jj) * BB + b0 + b], 0.f);
    }
    __syncthreads();
    const float bi = cb[tj * 4 + 0], bf = cb[tj * 4 + 1];
    const float bg = cb[tj * 4 + 2], bo = cb[tj * 4 + 3];

    unsigned lsense = 0;
    grid_barrier(&lsense);                   // #1

    float c0 = 0.f, c1 = 0.f;

    for (int t = 0; t < TT; ++t) {
        const int rb = t & 1, wb = rb ^ 1;

        for (int idx = tid; idx < 32 * IIN; idx += NTHR) {
            int r = idx / IIN, k = idx - r * IIN;
            Xs[idx] = x[((size_t)(b0 + r) * TT + t) * IIN + k];
        }
        __syncthreads();

        // input projection (scalar, K=17)
        float f00 = bi, f01 = bf, f02 = bg, f03 = bo;
        float f10 = bi, f11 = bf, f12 = bg, f13 = bo;
#pragma unroll
        for (int k = 0; k < IIN; ++k) {
            float a0 = Xs[tb * IIN + k], a1 = Xs[(tb + 16) * IIN + k];
            float w0 = Wi[(tj * 4 + 0) * IIN + k];
            float w1 = Wi[(tj * 4 + 1) * IIN + k];
            float w2 = Wi[(tj * 4 + 2) * IIN + k];
            float w3 = Wi[(tj * 4 + 3) * IIN + k];
            f00 = fmaf(a0, w0, f00); f01 = fmaf(a0, w1, f01);
            f02 = fmaf(a0, w2, f02); f03 = fmaf(a0, w3, f03);
            f10 = fmaf(a1, w0, f10); f11 = fmaf(a1, w1, f11);
            f12 = fmaf(a1, w2, f12); f13 = fmaf(a1, w3, f13);
        }

        // recurrent GEMM, K=512 in 2 chunks, persistent weights
        u64 a00 = 0, a01 = 0, a10 = 0, a11 = 0;
        const float* hprev = g_h0T[rb];
#pragma unroll 1
        for (int c = 0; c < 2; ++c) {
            const int k0 = c * 256;
            __syncthreads();
            stage_A<256, true>(As, hprev, k0, b0, tid);
            __syncthreads();
            compute_chunk<256>(As, Wp + k0 * 32, tb, tj, a00, a01, a10, a11);
        }

        // epilogue
        {
            float2 v0 = unpack2(a00), v1 = unpack2(a01);
            float gi = f00 + v0.x, gf = f01 + v0.y, gg = f02 + v1.x, go = f03 + v1.y;
            c0 = sigf(gf) * c0 + sigf(gi) * tanhf(gg);
            float h = sigf(go) * tanhf(c0);
            int b = b0 + tb;
            __stcg(&g_h0T[wb][(j0 + tj) * BB + b], h);
            __stcg(&g_y0T[((size_t)t * HH + j0 + tj) * BB + b], h);
        }
        {
            float2 v0 = unpack2(a10), v1 = unpack2(a11);
            float gi = f10 + v0.x, gf = f11 + v0.y, gg = f12 + v1.x, go = f13 + v1.y;
            c1 = sigf(gf) * c1 + sigf(gi) * tanhf(gg);
            float h = sigf(go) * tanhf(c1);
            int b = b0 + tb + 16;
            __stcg(&g_h0T[wb][(j0 + tj) * BB + b], h);
            __stcg(&g_y0T[((size_t)t * HH + j0 + tj) * BB + b], h);
        }

        grid_barrier(&lsense);               // #2..#1025
    }
    grid_barrier(&lsense);                   // #1026 (even)
}

// ================= Layer 1 =================
// smem: Wp[512*32]u64=128KB | As[128*32]u64=32KB | Wst[128*32]u64=32KB | cb[64]f
#define SM1_BYTES ((16384 + 4096 + 4096) * 8 + 64 * 4)

extern "C" __global__ void __launch_bounds__(NTHR, 1)
lstm_l1(const float* __restrict__ wih, const float* __restrict__ whh,
        const float* __restrict__ bih, const float* __restrict__ bhh)
{
    extern __shared__ u64 sm1[];
    u64*   Wp  = sm1;                        // 16384 u64 (whh1, persistent)
    u64*   As  = sm1 + 16384;                // 4096 u64
    u64*   Wst = sm1 + 16384 + 4096;         // 4096 u64 (wih1 streamed chunk)
    float* cb  = (float*)(sm1 + 16384 + 8192);

    const int tid = threadIdx.x;
    const int tb = tid & 15, tj = tid >> 4;
    const int b0 = (blockIdx.x >> 5) * 32;
    const int j0 = (blockIdx.x & 31) * 16;

    load_Wpers(Wp, whh, j0, tid);
    if (tid < 64) {
        int row = (tid & 3) * HH + j0 + (tid >> 2);
        cb[tid] = bih[row] + bhh[row];
    }
    for (int idx = tid; idx < 16 * 32; idx += NTHR) {
        int jj = idx >> 5, b = idx & 31;
        __stcg(&g_h1T[0][(j0 + jj) * BB + b0 + b], 0.f);
    }
    __syncthreads();
    const float bi = cb[tj * 4 + 0], bf = cb[tj * 4 + 1];
    const float bg = cb[tj * 4 + 2], bo = cb[tj * 4 + 3];

    unsigned lsense = 0;
    grid_barrier(&lsense);

    float c0 = 0.f, c1 = 0.f;

    for (int t = 0; t < TT; ++t) {
        const int rb = t & 1, wb = rb ^ 1;

        u64 a00 = 0, a01 = 0, a10 = 0, a11 = 0;

        // input-projection part: A = y0[t] (K=512), W = wih1 streamed
        const float* ysrc = g_y0T + (size_t)t * HH * BB;
#pragma unroll 1
        for (int c = 0; c < 4; ++c) {
            const int k0 = c * 128;
            __syncthreads();
#pragma unroll
            for (int uu = 0; uu < 4; ++uu) {
                int idx = tid + uu * NTHR;
                int gp = idx >> 5, kq = idx & 31;
                int r0 = gp * 2, r1 = r0 + 1;
                int row0 = (r0 & 3) * HH + j0 + (r0 >> 2);
                int row1 = (r1 & 3) * HH + j0 + (r1 >> 2);
                float4 wa = *(const float4*)(wih + (size_t)row0 * HH + k0 + kq * 4);
                float4 wb4 = *(const float4*)(wih + (size_t)row1 * HH + k0 + kq * 4);
                int kb = kq * 4;
                Wst[(kb + 0) * 32 + gp] = pack2(wa.x, wb4.x);
                Wst[(kb + 1) * 32 + gp] = pack2(wa.y, wb4.y);
                Wst[(kb + 2) * 32 + gp] = pack2(wa.z, wb4.z);
                Wst[(kb + 3) * 32 + gp] = pack2(wa.w, wb4.w);
            }
            stage_A<128, false>(As, ysrc, k0, b0, tid);
            __syncthreads();
            compute_chunk<128>(As, Wst, tb, tj, a00, a01, a10, a11);
        }

        // recurrent part: A = h_{t-1} (K=512), W = whh1 persistent
        const float* hprev = g_h1T[rb];
#pragma unroll 1
        for (int c = 0; c < 4; ++c) {
            const int k0 = c * 128;
            __syncthreads();
            stage_A<128, true>(As, hprev, k0, b0, tid);
            __syncthreads();
            compute_chunk<128>(As, Wp + k0 * 32, tb, tj, a00, a01, a10, a11);
        }

        {
            float2 v0 = unpack2(a00), v1 = unpack2(a01);
            float gi = bi + v0.x, gf = bf + v0.y, gg = bg + v1.x, go = bo + v1.y;
            c0 = sigf(gf) * c0 + sigf(gi) * tanhf(gg);
            float h = sigf(go) * tanhf(c0);
            __stcg(&g_h1T[wb][(j0 + tj) * BB + b0 + tb], h);
        }
        {
            float2 v0 = unpack2(a10), v1 = unpack2(a11);
            float gi = bi + v0.x, gf = bf + v0.y, gg = bg + v1.x, go = bo + v1.y;
            c1 = sigf(gf) * c1 + sigf(gi) * tanhf(gg);
            float h = sigf(go) * tanhf(c1);
            __stcg(&g_h1T[wb][(j0 + tj) * BB + b0 + tb + 16], h);
        }

        grid_barrier(&lsense);
    }
    grid_barrier(&lsense);                   // even parity; final h in g_h1T[0]
}

// ---------------- final linear ----------------
extern "C" __global__ void final_linear(const float* __restrict__ lin_w,
                                        const float* __restrict__ lin_b,
                                        float* __restrict__ out)
{
    __shared__ float wrow[HH];
    int o = blockIdx.x;
    for (int k = threadIdx.x; k < HH; k += 128) wrow[k] = lin_w[o * HH + k];
    __syncthreads();
    int b = threadIdx.x;
    float acc0 = 0.f, acc1 = 0.f, acc2 = 0.f, acc3 = 0.f;
#pragma unroll 4
    for (int j = 0; j < HH; j += 4) {
        acc0 = fmaf(g_h1T[0][(j + 0) * BB + b], wrow[j + 0], acc0);
        acc1 = fmaf(g_h1T[0][(j + 1) * BB + b], wrow[j + 1], acc1);
        acc2 = fmaf(g_h1T[0][(j + 2) * BB + b], wrow[j + 2], acc2);
        acc3 = fmaf(g_h1T[0][(j + 3) * BB + b], wrow[j + 3], acc3);
    }
    out[b * OOUT + o] = acc0 + acc1 + acc2 + acc3 + lin_b[o];
}

// ---------------- launch ----------------
extern "C" void kernel_launch(void* const* d_in, const int* in_sizes, int n_in,
                              void* d_out, int out_size)
{
    const float* x     = (const float*)d_in[0];
    const float* wih0  = (const float*)d_in[1];
    const float* whh0  = (const float*)d_in[2];
    const float* bih0  = (const float*)d_in[3];
    const float* bhh0  = (const float*)d_in[4];
    const float* wih1  = (const float*)d_in[5];
    const float* whh1  = (const float*)d_in[6];
    const float* bih1  = (const float*)d_in[7];
    const float* bhh1  = (const float*)d_in[8];
    const float* lin_w = (const float*)d_in[9];
    const float* lin_b = (const float*)d_in[10];

    cudaFuncSetAttribute(lstm_l0, cudaFuncAttributeMaxDynamicSharedMemorySize, SM0_BYTES);
    cudaFuncSetAttribute(lstm_l1, cudaFuncAttributeMaxDynamicSharedMemorySize, SM1_BYTES);

    lstm_l0<<<NBLK, NTHR, SM0_BYTES>>>(x, wih0, whh0, bih0, bhh0);
    lstm_l1<<<NBLK, NTHR, SM1_BYTES>>>(wih1, whh1, bih1, bhh1);
    final_linear<<<OOUT, 128>>>(lin_w, lin_b, (float*)d_out);
}

// round 3
// speedup vs baseline: 1.0033x; 1.0033x over previous
#include <cuda_runtime.h>
#include <cstdint>

#define BB   128
#define TT   1024
#define HH   512
#define IIN  17
#define OOUT 17
#define NBLK 128
#define NTHR 256

typedef unsigned long long u64;

// ---------------- device scratch ----------------
// h and y0 stored TRANSPOSED: [j][b] so GEMM A-staging is coalesced.
__device__ float g_h0T[2][HH * BB];
__device__ float g_h1T[2][HH * BB];
__device__ float g_y0T[(size_t)TT * HH * BB];   // 256MB, [t][j][b]

__device__ unsigned          g_bar_cnt = 0;
__device__ volatile unsigned g_bar_sense = 0;

// ---------------- grid-wide spin barrier (sense reversing) ----------------
__device__ __forceinline__ void grid_barrier(unsigned* lsense)
{
    __syncthreads();
    if (threadIdx.x == 0) {
        unsigned s = *lsense ^ 1u;
        *lsense = s;
        __threadfence();
        unsigned prev = atomicAdd(&g_bar_cnt, 1u);
        if (prev == NBLK - 1u) {
            atomicExch(&g_bar_cnt, 0u);
            __threadfence();
            g_bar_sense = s;
        } else {
            while (g_bar_sense != s) { }
        }
        __threadfence();
    }
    __syncthreads();
}

// ---------------- packed f32x2 helpers ----------------
__device__ __forceinline__ u64 ffma2(u64 a, u64 b, u64 c) {
    u64 d;
    asm("fma.rn.f32x2 %0, %1, %2, %3;" : "=l"(d) : "l"(a), "l"(b), "l"(c));
    return d;
}
__device__ __forceinline__ u64 pack2(float x, float y) {
    u64 r; asm("mov.b64 %0, {%1, %2};" : "=l"(r) : "f"(x), "f"(y)); return r;
}
__device__ __forceinline__ float2 unpack2(u64 v) {
    float2 f; asm("mov.b64 {%0, %1}, %2;" : "=f"(f.x), "=f"(f.y) : "l"(v)); return f;
}
__device__ __forceinline__ float sigf(float v) { return 1.f / (1.f + expf(-v)); }

// ---------------- A staging: global [k][BB] fp32 -> smem [kk][32] dup'd pairs ----
// smem slot index: kk*32 + (b&15)*2 + (b>>4)  (pairs batches b and b+16 adjacently)
template<int KC, bool LDCG>
__device__ __forceinline__ void stage_A(u64* __restrict__ As,
                                        const float* __restrict__ src,
                                        int k0, int b0, int tid)
{
#pragma unroll
    for (int u = 0; u < (KC * 8) / NTHR; ++u) {
        int idx = tid + u * NTHR;
        int kk = idx >> 3, q = idx & 7;
        const float4* p = (const float4*)(src + (size_t)(k0 + kk) * BB + b0) + q;
        float4 v = LDCG ? __ldcg(p) : *p;
        int b = q * 4;
        int base = kk * 32 + (b & 15) * 2 + (b >> 4);
        As[base + 0] = pack2(v.x, v.x);
        As[base + 2] = pack2(v.y, v.y);
        As[base + 4] = pack2(v.z, v.z);
        As[base + 6] = pack2(v.w, v.w);
    }
}

// ---------------- FFMA2 GEMM chunk ----------------
// As: [kk][32] dup'd h pairs; W: [kk][32] gate-pair weights.
// Thread owns cell tj (gate pairs 2tj,2tj+1) x batches (tb, tb+16).
template<int KC>
__device__ __forceinline__ void compute_chunk(const u64* __restrict__ As,
                                              const u64* __restrict__ W,
                                              int tb, int tj,
                                              u64& a00, u64& a01, u64& a10, u64& a11)
{
#pragma unroll 8
    for (int kk = 0; kk < KC; ++kk) {
        ulonglong2 av = *(const ulonglong2*)(As + kk * 32 + tb * 2);
        ulonglong2 wv = *(const ulonglong2*)(W  + kk * 32 + tj * 2);
        a00 = ffma2(av.x, wv.x, a00);
        a01 = ffma2(av.x, wv.y, a01);
        a10 = ffma2(av.y, wv.x, a10);
        a11 = ffma2(av.y, wv.y, a11);
    }
}

// ---------------- persistent weight pack: W[2048,512] -> smem [k][32] gate pairs
__device__ __forceinline__ void load_Wpers(u64* __restrict__ Wp,
                                           const float* __restrict__ w,
                                           int j0, int tid)
{
    for (int idx = tid; idx < HH * 32; idx += NTHR) {
        int k = idx >> 5, gp = idx & 31;
        int r0 = gp * 2, r1 = r0 + 1;
        int row0 = (r0 & 3) * HH + j0 + (r0 >> 2);
        int row1 = (r1 & 3) * HH + j0 + (r1 >> 2);
        Wp[(size_t)k * 32 + gp] = pack2(w[(size_t)row0 * HH + k],
                                        w[(size_t)row1 * HH + k]);
    }
}

// ================= Layer 0 =================
// smem: Wp[512*32]u64=128KB | As[256*32]u64=64KB | Wi[64*17]f | Xs[32*17]f | cb[64]f
#define SM0_BYTES ((16384 + 8192) * 8 + (1088 + 544 + 64) * 4)

extern "C" __global__ void __launch_bounds__(NTHR, 1)
lstm_l0(const float* __restrict__ x,
        const float* __restrict__ wih, const float* __restrict__ whh,
        const float* __restrict__ bih, const float* __restrict__ bhh)
{
    extern __shared__ u64 sm0[];
    u64*   Wp = sm0;                         // 16384 u64
    u64*   As = sm0 + 16384;                 // 8192 u64
    float* Wi = (float*)(sm0 + 16384 + 8192);
    float* Xs = Wi + 64 * IIN;
    float* cb = Xs + 32 * IIN;

    const int tid = threadIdx.x;
    const int tb = tid & 15, tj = tid >> 4;
    const int b0 = (blockIdx.x >> 5) * 32;
    const int j0 = (blockIdx.x & 31) * 16;

    load_Wpers(Wp, whh, j0, tid);
    for (int idx = tid; idx < 64 * IIN; idx += NTHR) {
        int r = idx / IIN, k = idx - r * IIN;
        Wi[idx] = wih[(size_t)((r & 3) * HH + j0 + (r >> 2)) * IIN + k];
    }
    if (tid < 64) {
        int row = (tid & 3) * HH + j0 + (tid >> 2);
        cb[tid] = bih[row] + bhh[row];
    }
    for (int idx = tid; idx < 16 * 32; idx += NTHR) {
        int jj = idx >> 5, b = idx & 31;
        __stcg(&g_h0T[0][(j0 + jj) * BB + b0 + b], 0.f);
    }
    __syncthreads();
    const float bi = cb[tj * 4 + 0], bf = cb[tj * 4 + 1];
    const float bg = cb[tj * 4 + 2], bo = cb[tj * 4 + 3];

    unsigned lsense = 0;
    grid_barrier(&lsense);                   // #1

    float c0 = 0.f, c1 = 0.f;

    for (int t = 0; t < TT; ++t) {
        const int rb = t & 1, wb = rb ^ 1;

        for (int idx = tid; idx < 32 * IIN; idx += NTHR) {
            int r = idx / IIN, k = idx - r * IIN;
            Xs[idx] = x[((size_t)(b0 + r) * TT + t) * IIN + k];
        }
        __syncthreads();

        // input projection (scalar, K=17)
        float f00 = bi, f01 = bf, f02 = bg, f03 = bo;
        float f10 = bi, f11 = bf, f12 = bg, f13 = bo;
#pragma unroll
        for (int k = 0; k < IIN; ++k) {
            float a0 = Xs[tb * IIN + k], a1 = Xs[(tb + 16) * IIN + k];
            float w0 = Wi[(tj * 4 + 0) * IIN + k];
            float w1 = Wi[(tj * 4 + 1) * IIN + k];
            float w2 = Wi[(tj * 4 + 2) * IIN + k];
            float w3 = Wi[(tj * 4 + 3) * IIN + k];
            f00 = fmaf(a0, w0, f00); f01 = fmaf(a0, w1, f01);
            f02 = fmaf(a0, w2, f02); f03 = fmaf(a0, w3, f03);
            f10 = fmaf(a1, w0, f10); f11 = fmaf(a1, w1, f11);
            f12 = fmaf(a1, w2, f12); f13 = fmaf(a1, w3, f13);
        }

        // recurrent GEMM, K=512 in 2 chunks, persistent weights
        u64 a00 = 0, a01 = 0, a10 = 0, a11 = 0;
        const float* hprev = g_h0T[rb];
#pragma unroll 1
        for (int c = 0; c < 2; ++c) {
            const int k0 = c * 256;
            __syncthreads();
            stage_A<256, true>(As, hprev, k0, b0, tid);
            __syncthreads();
            compute_chunk<256>(As, Wp + k0 * 32, tb, tj, a00, a01, a10, a11);
        }

        // epilogue
        {
            float2 v0 = unpack2(a00), v1 = unpack2(a01);
            float gi = f00 + v0.x, gf = f01 + v0.y, gg = f02 + v1.x, go = f03 + v1.y;
            c0 = sigf(gf) * c0 + sigf(gi) * tanhf(gg);
            float h = sigf(go) * tanhf(c0);
            int b = b0 + tb;
            __stcg(&g_h0T[wb][(j0 + tj) * BB + b], h);
            __stcg(&g_y0T[((size_t)t * HH + j0 + tj) * BB + b], h);
        }
        {
            float2 v0 = unpack2(a10), v1 = unpack2(a11);
            float gi = f10 + v0.x, gf = f11 + v0.y, gg = f12 + v1.x, go = f13 + v1.y;
            c1 = sigf(gf) * c1 + sigf(gi) * tanhf(gg);
            float h = sigf(go) * tanhf(c1);
            int b = b0 + tb + 16;
            __stcg(&g_h0T[wb][(j0 + tj) * BB + b], h);
            __stcg(&g_y0T[((size_t)t * HH + j0 + tj) * BB + b], h);
        }

        grid_barrier(&lsense);               // #2..#1025
    }
    grid_barrier(&lsense);                   // #1026 (even)
}

// ================= Layer 1 =================
// smem: Wp[512*32]u64=128KB | As[128*32]u64=32KB | Wst[128*32]u64=32KB | cb[64]f
#define SM1_BYTES ((16384 + 4096 + 4096) * 8 + 64 * 4)

extern "C" __global__ void __launch_bounds__(NTHR, 1)
lstm_l1(const float* __restrict__ wih, const float* __restrict__ whh,
        const float* __restrict__ bih, const float* __restrict__ bhh)
{
    extern __shared__ u64 sm1[];
    u64*   Wp  = sm1;                        // 16384 u64 (whh1, persistent)
    u64*   As  = sm1 + 16384;                // 4096 u64
    u64*   Wst = sm1 + 16384 + 4096;         // 4096 u64 (wih1 streamed chunk)
    float* cb  = (float*)(sm1 + 16384 + 8192);

    const int tid = threadIdx.x;
    const int tb = tid & 15, tj = tid >> 4;
    const int b0 = (blockIdx.x >> 5) * 32;
    const int j0 = (blockIdx.x & 31) * 16;

    load_Wpers(Wp, whh, j0, tid);
    if (tid < 64) {
        int row = (tid & 3) * HH + j0 + (tid >> 2);
        cb[tid] = bih[row] + bhh[row];
    }
    for (int idx = tid; idx < 16 * 32; idx += NTHR) {
        int jj = idx >> 5, b = idx & 31;
        __stcg(&g_h1T[0][(j0 + jj) * BB + b0 + b], 0.f);
    }
    __syncthreads();
    const float bi = cb[tj * 4 + 0], bf = cb[tj * 4 + 1];
    const float bg = cb[tj * 4 + 2], bo = cb[tj * 4 + 3];

    unsigned lsense = 0;
    grid_barrier(&lsense);

    float c0 = 0.f, c1 = 0.f;

    for (int t = 0; t < TT; ++t) {
        const int rb = t & 1, wb = rb ^ 1;

        u64 a00 = 0, a01 = 0, a10 = 0, a11 = 0;

        // input-projection part: A = y0[t] (K=512), W = wih1 streamed
        const float* ysrc = g_y0T + (size_t)t * HH * BB;
#pragma unroll 1
        for (int c = 0; c < 4; ++c) {
            const int k0 = c * 128;
            __syncthreads();
#pragma unroll
            for (int uu = 0; uu < 4; ++uu) {
                int idx = tid + uu * NTHR;
                int gp = idx >> 5, kq = idx & 31;
                int r0 = gp * 2, r1 = r0 + 1;
                int row0 = (r0 & 3) * HH + j0 + (r0 >> 2);
                int row1 = (r1 & 3) * HH + j0 + (r1 >> 2);
                float4 wa = *(const float4*)(wih + (size_t)row0 * HH + k0 + kq * 4);
                float4 wb4 = *(const float4*)(wih + (size_t)row1 * HH + k0 + kq * 4);
                int kb = kq * 4;
                Wst[(kb + 0) * 32 + gp] = pack2(wa.x, wb4.x);
                Wst[(kb + 1) * 32 + gp] = pack2(wa.y, wb4.y);
                Wst[(kb + 2) * 32 + gp] = pack2(wa.z, wb4.z);
                Wst[(kb + 3) * 32 + gp] = pack2(wa.w, wb4.w);
            }
            stage_A<128, false>(As, ysrc, k0, b0, tid);
            __syncthreads();
            compute_chunk<128>(As, Wst, tb, tj, a00, a01, a10, a11);
        }

        // recurrent part: A = h_{t-1} (K=512), W = whh1 persistent
        const float* hprev = g_h1T[rb];
#pragma unroll 1
        for (int c = 0; c < 4; ++c) {
            const int k0 = c * 128;
            __syncthreads();
            stage_A<128, true>(As, hprev, k0, b0, tid);
            __syncthreads();
            compute_chunk<128>(As, Wp + k0 * 32, tb, tj, a00, a01, a10, a11);
        }

        {
            float2 v0 = unpack2(a00), v1 = unpack2(a01);
            float gi = bi + v0.x, gf = bf + v0.y, gg = bg + v1.x, go = bo + v1.y;
            c0 = sigf(gf) * c0 + sigf(gi) * tanhf(gg);
            float h = sigf(go) * tanhf(c0);
            __stcg(&g_h1T[wb][(j0 + tj) * BB + b0 + tb], h);
        }
        {
            float2 v0 = unpack2(a10), v1 = unpack2(a11);
            float gi = bi + v0.x, gf = bf + v0.y, gg = bg + v1.x, go = bo + v1.y;
            c1 = sigf(gf) * c1 + sigf(gi) * tanhf(gg);
            float h = sigf(go) * tanhf(c1);
            __stcg(&g_h1T[wb][(j0 + tj) * BB + b0 + tb + 16], h);
        }

        grid_barrier(&lsense);
    }
    grid_barrier(&lsense);                   // even parity; final h in g_h1T[0]
}

// ---------------- final linear ----------------
extern "C" __global__ void final_linear(const float* __restrict__ lin_w,
                                        const float* __restrict__ lin_b,
                                        float* __restrict__ out)
{
    __shared__ float wrow[HH];
    int o = blockIdx.x;
    for (int k = threadIdx.x; k < HH; k += 128) wrow[k] = lin_w[o * HH + k];
    __syncthreads();
    int b = threadIdx.x;
    float acc0 = 0.f, acc1 = 0.f, acc2 = 0.f, acc3 = 0.f;
#pragma unroll 4
    for (int j = 0; j < HH; j += 4) {
        acc0 = fmaf(g_h1T[0][(j + 0) * BB + b], wrow[j + 0], acc0);
        acc1 = fmaf(g_h1T[0][(j + 1) * BB + b], wrow[j + 1], acc1);
        acc2 = fmaf(g_h1T[0][(j + 2) * BB + b], wrow[j + 2], acc2);
        acc3 = fmaf(g_h1T[0][(j + 3) * BB + b], wrow[j + 3], acc3);
    }
    out[b * OOUT + o] = acc0 + acc1 + acc2 + acc3 + lin_b[o];
}

// ---------------- launch ----------------
extern "C" void kernel_launch(void* const* d_in, const int* in_sizes, int n_in,
                              void* d_out, int out_size)
{
    const float* x     = (const float*)d_in[0];
    const float* wih0  = (const float*)d_in[1];
    const float* whh0  = (const float*)d_in[2];
    const float* bih0  = (const float*)d_in[3];
    const float* bhh0  = (const float*)d_in[4];
    const float* wih1  = (const float*)d_in[5];
    const float* whh1  = (const float*)d_in[6];
    const float* bih1  = (const float*)d_in[7];
    const float* bhh1  = (const float*)d_in[8];
    const float* lin_w = (const float*)d_in[9];
    const float* lin_b = (const float*)d_in[10];

    cudaFuncSetAttribute(lstm_l0, cudaFuncAttributeMaxDynamicSharedMemorySize, SM0_BYTES);
    cudaFuncSetAttribute(lstm_l1, cudaFuncAttributeMaxDynamicSharedMemorySize, SM1_BYTES);

    lstm_l0<<<NBLK, NTHR, SM0_BYTES>>>(x, wih0, whh0, bih0, bhh0);
    lstm_l1<<<NBLK, NTHR, SM1_BYTES>>>(wih1, whh1, bih1, bhh1);
    final_linear<<<OOUT, 128>>>(lin_w, lin_b, (float*)d_out);
}

// round 4
// speedup vs baseline: 1.8346x; 1.8285x over previous
#include <cuda_runtime.h>
#include <cstdint>

#define BB   128
#define TT   1024
#define HH   512
#define IIN  17
#define OOUT 17
#define NBLK 128
#define NTHR 256

// B'' slot: 64 k-tiles x 128 batch x 16 floats {hi(k),hi(k+4),lo(k),lo(k+4)} per (kt,b,p)
#define BSLOT (64 * 128 * 16)          // 131072 floats = 512KB
// A' matrix: 128 m-tiles x 64 k-tiles x 32 lanes x 8 floats {hi[4], lo[4]}
#define AMAT  (128 * 64 * 32 * 8)      // 2,097,152 floats = 8MB

// ---------------- device scratch ----------------
__device__ float g_A0 [AMAT];                    // whh0 split, frag order
__device__ float g_A1i[AMAT];                    // wih1 split
__device__ float g_A1h[AMAT];                    // whh1 split
__device__ float g_y0b[(size_t)(TT + 1) * BSLOT]; // layer0 h / layer1 input, slot t+1
__device__ float g_h1b[2][BSLOT];                // layer1 h ping-pong

__device__ unsigned          g_bar_cnt = 0;
__device__ volatile unsigned g_bar_sense = 0;

// ---------------- grid barrier ----------------
__device__ __forceinline__ void grid_barrier(unsigned* lsense)
{
    __syncthreads();
    if (threadIdx.x == 0) {
        unsigned s = *lsense ^ 1u;
        *lsense = s;
        __threadfence();
        unsigned prev = atomicAdd(&g_bar_cnt, 1u);
        if (prev == NBLK - 1u) {
            atomicExch(&g_bar_cnt, 0u);
            __threadfence();
            g_bar_sense = s;
        } else {
            while (g_bar_sense != s) { }
        }
        __threadfence();
    }
    __syncthreads();
}

// ---------------- tf32 helpers ----------------
__device__ __forceinline__ float2 split_tf32(float w)
{
    uint32_t hb;
    asm("cvt.rna.tf32.f32 %0, %1;" : "=r"(hb) : "f"(w));
    float hi = __uint_as_float(hb);
    float r = w - hi;                  // exact (Sterbenz)
    uint32_t lb;
    asm("cvt.rna.tf32.f32 %0, %1;" : "=r"(lb) : "f"(r));
    return make_float2(hi, __uint_as_float(lb));
}

__device__ __forceinline__ void mma_tf32(float c[4], const uint32_t a[4],
                                         uint32_t b0, uint32_t b1)
{
    asm("mma.sync.aligned.m16n8k8.row.col.f32.tf32.tf32.f32 "
        "{%0,%1,%2,%3}, {%4,%5,%6,%7}, {%8,%9}, {%0,%1,%2,%3};"
        : "+f"(c[0]), "+f"(c[1]), "+f"(c[2]), "+f"(c[3])
        : "r"(a[0]), "r"(a[1]), "r"(a[2]), "r"(a[3]), "r"(b0), "r"(b1));
}

__device__ __forceinline__ float sigf(float v) { return 1.f / (1.f + expf(-v)); }

// ---------------- weight prep: split + fragment reorder ----------------
// Row m' = cell*4 + gate (interleaved); source row = gate*512 + cell.
extern "C" __global__ void prep_weights(const float* __restrict__ whh0,
                                        const float* __restrict__ wih1,
                                        const float* __restrict__ whh1)
{
    const int ME = 2048 * 512;
    int idx = blockIdx.x * blockDim.x + threadIdx.x;
    if (idx >= 3 * ME) return;
    int mat = idx / ME, e = idx % ME;
    int mp = e >> 9, k = e & 511;
    int cell = mp >> 2, g = mp & 3;
    const float* W = (mat == 0) ? whh0 : (mat == 1) ? wih1 : whh1;
    float2 s = split_tf32(W[(size_t)(g * HH + cell) * HH + k]);
    int mt = mp >> 4, rl = mp & 15;
    int kt = k >> 3,  cl = k & 7;
    int a = (rl >> 3) | ((cl >> 2) << 1);
    int lane = (rl & 7) * 4 + (cl & 3);
    float* dst = (mat == 0) ? g_A0 : (mat == 1) ? g_A1i : g_A1h;
    size_t base = (((size_t)mt * 64 + kt) * 32 + lane) * 8;
    dst[base + a]     = s.x;
    dst[base + 4 + a] = s.y;
}

// ---------------- epilogue helpers ----------------
// Write block's h tile (hsm_hi/lo[16][32]) coalesced into B'' layout at dst.
__device__ __forceinline__ void store_h_tile(float* __restrict__ dst,
                                             const float* __restrict__ hsm_hi,
                                             const float* __restrict__ hsm_lo,
                                             int mb, int b0, int tid)
{
#pragma unroll
    for (int f = tid; f < 1024; f += NTHR) {
        int ktl = f >> 9, ff = f & 511;
        int b = ff >> 4, rem = ff & 15, p = rem >> 2, q = rem & 3;
        int jloc = ktl * 8 + p + (q & 1) * 4;
        float v = (q < 2) ? hsm_hi[jloc * 32 + b] : hsm_lo[jloc * 32 + b];
        int ktg = 2 * mb + ktl;
        __stcg(&dst[((size_t)(ktg * 128 + b0 + b) << 4) + (p << 2) + q], v);
    }
}

__device__ __forceinline__ void zero_h_tile(float* __restrict__ dst,
                                            int mb, int b0, int tid)
{
#pragma unroll
    for (int f = tid; f < 1024; f += NTHR) {
        int ktl = f >> 9, ff = f & 511;
        int b = ff >> 4, rem = ff & 15, p = rem >> 2, q = rem & 3;
        int ktg = 2 * mb + ktl;
        __stcg(&dst[((size_t)(ktg * 128 + b0 + b) << 4) + (p << 2) + q], 0.f);
    }
}

// ---------------- mma sweep over 64 k-tiles ----------------
// acc[nt][term][4]; A from frag-ordered Awarp; B from B''-ordered Bt (via L2).
__device__ __forceinline__ void mma_sweep(float acc[2][3][4],
                                          const float4* __restrict__ A4,
                                          const float* __restrict__ Bt,
                                          int lane, int ti, int bg0, int bg1)
{
    const float4* B4 = (const float4*)Bt;
#pragma unroll 4
    for (int kt = 0; kt < 64; ++kt) {
        float4 ah = A4[(kt << 6) + (lane << 1)];
        float4 al = A4[(kt << 6) + (lane << 1) + 1];
        const uint32_t* ahp = (const uint32_t*)&ah;
        const uint32_t* alp = (const uint32_t*)&al;
        float4 bv0 = __ldcg(&B4[((kt << 7) + bg0) * 4 + ti]);
        float4 bv1 = __ldcg(&B4[((kt << 7) + bg1) * 4 + ti]);
        mma_tf32(acc[0][0], ahp, __float_as_uint(bv0.x), __float_as_uint(bv0.y));
        mma_tf32(acc[0][1], ahp, __float_as_uint(bv0.z), __float_as_uint(bv0.w));
        mma_tf32(acc[0][2], alp, __float_as_uint(bv0.x), __float_as_uint(bv0.y));
        mma_tf32(acc[1][0], ahp, __float_as_uint(bv1.x), __float_as_uint(bv1.y));
        mma_tf32(acc[1][1], ahp, __float_as_uint(bv1.z), __float_as_uint(bv1.w));
        mma_tf32(acc[1][2], alp, __float_as_uint(bv1.x), __float_as_uint(bv1.y));
    }
}

// D frags -> smem gates[64][33]
__device__ __forceinline__ void sts_D(float* __restrict__ gsm, float acc[2][3][4],
                                      int wm, int wn, int gi, int ti)
{
#pragma unroll
    for (int nt = 0; nt < 2; ++nt) {
        float v0 = acc[nt][0][0] + acc[nt][1][0] + acc[nt][2][0];
        float v1 = acc[nt][0][1] + acc[nt][1][1] + acc[nt][2][1];
        float v2 = acc[nt][0][2] + acc[nt][1][2] + acc[nt][2][2];
        float v3 = acc[nt][0][3] + acc[nt][1][3] + acc[nt][2][3];
        int col = wn * 16 + nt * 8 + 2 * ti;
        int r0 = wm * 16 + gi;
        gsm[r0 * 33 + col]       = v0;
        gsm[r0 * 33 + col + 1]   = v1;
        gsm[(r0 + 8) * 33 + col]     = v2;
        gsm[(r0 + 8) * 33 + col + 1] = v3;
    }
}

// ================= Layer 0 =================
extern "C" __global__ void __launch_bounds__(NTHR, 1)
lstm_l0(const float* __restrict__ x,
        const float* __restrict__ wih, const float* __restrict__ bih,
        const float* __restrict__ bhh)
{
    __shared__ float gsm[64 * 33];
    __shared__ float Wi[64 * IIN];
    __shared__ float Xs[32 * IIN];
    __shared__ float cb[64];
    __shared__ float hsm_hi[16 * 32];
    __shared__ float hsm_lo[16 * 32];

    const int tid = threadIdx.x;
    const int lane = tid & 31, wid = tid >> 5;
    const int wm = wid & 3, wn = wid >> 2;
    const int gi = lane >> 2, ti = lane & 3;
    const int mb = blockIdx.x >> 2, nb = blockIdx.x & 3;
    const int b0 = nb * 32;

    // prologue: Wi (wih0 slice, interleaved rows), combined bias, zero y0 slot 0
    for (int idx = tid; idx < 64 * IIN; idx += NTHR) {
        int r = idx / IIN, k = idx - r * IIN;
        int cell = mb * 16 + (r >> 2), g = r & 3;
        Wi[idx] = wih[(size_t)(g * HH + cell) * IIN + k];
    }
    if (tid < 64) {
        int row = (tid & 3) * HH + mb * 16 + (tid >> 2);
        cb[tid] = bih[row] + bhh[row];
    }
    zero_h_tile(g_y0b, mb, b0, tid);

    unsigned lsense = 0;
    grid_barrier(&lsense);                           // #1

    const float4* A4 = (const float4*)(g_A0 + (size_t)(mb * 4 + wm) * 16384);
    const int bg0 = b0 + wn * 16 + gi;
    const int bg1 = bg0 + 8;
    const int jj = tid >> 4, bl = tid & 15;
    float cst[2] = {0.f, 0.f};

    for (int t = 0; t < TT; ++t) {
        // stage x_t
        for (int idx = tid; idx < 32 * IIN; idx += NTHR) {
            int r = idx / IIN, k = idx - r * IIN;
            Xs[idx] = x[((size_t)(b0 + r) * TT + t) * IIN + k];
        }

        float acc[2][3][4];
#pragma unroll
        for (int nt = 0; nt < 2; ++nt)
#pragma unroll
            for (int s = 0; s < 3; ++s)
#pragma unroll
                for (int i = 0; i < 4; ++i) acc[nt][s][i] = 0.f;

        mma_sweep(acc, A4, g_y0b + (size_t)t * BSLOT, lane, ti, bg0, bg1);
        sts_D(gsm, acc, wm, wn, gi, ti);
        __syncthreads();

        // cell update: thread owns cell jj, batches bl and bl+16
#pragma unroll
        for (int u = 0; u < 2; ++u) {
            int b = bl + u * 16;
            float s0 = cb[jj * 4 + 0], s1 = cb[jj * 4 + 1];
            float s2 = cb[jj * 4 + 2], s3 = cb[jj * 4 + 3];
#pragma unroll
            for (int k = 0; k < IIN; ++k) {
                float xv = Xs[b * IIN + k];
                s0 = fmaf(Wi[(jj * 4 + 0) * IIN + k], xv, s0);
                s1 = fmaf(Wi[(jj * 4 + 1) * IIN + k], xv, s1);
                s2 = fmaf(Wi[(jj * 4 + 2) * IIN + k], xv, s2);
                s3 = fmaf(Wi[(jj * 4 + 3) * IIN + k], xv, s3);
            }
            s0 += gsm[(jj * 4 + 0) * 33 + b];
            s1 += gsm[(jj * 4 + 1) * 33 + b];
            s2 += gsm[(jj * 4 + 2) * 33 + b];
            s3 += gsm[(jj * 4 + 3) * 33 + b];
            cst[u] = sigf(s1) * cst[u] + sigf(s0) * tanhf(s2);
            float h = sigf(s3) * tanhf(cst[u]);
            float2 hs = split_tf32(h);
            hsm_hi[jj * 32 + b] = hs.x;
            hsm_lo[jj * 32 + b] = hs.y;
        }
        __syncthreads();
        store_h_tile(g_y0b + (size_t)(t + 1) * BSLOT, hsm_hi, hsm_lo, mb, b0, tid);
        grid_barrier(&lsense);                       // #2..#1025
    }
    grid_barrier(&lsense);                           // #1026 (even)
}

// ================= Layer 1 =================
extern "C" __global__ void __launch_bounds__(NTHR, 1)
lstm_l1(const float* __restrict__ bih, const float* __restrict__ bhh)
{
    __shared__ float gsm[64 * 33];
    __shared__ float cb[64];
    __shared__ float hsm_hi[16 * 32];
    __shared__ float hsm_lo[16 * 32];

    const int tid = threadIdx.x;
    const int lane = tid & 31, wid = tid >> 5;
    const int wm = wid & 3, wn = wid >> 2;
    const int gi = lane >> 2, ti = lane & 3;
    const int mb = blockIdx.x >> 2, nb = blockIdx.x & 3;
    const int b0 = nb * 32;

    if (tid < 64) {
        int row = (tid & 3) * HH + mb * 16 + (tid >> 2);
        cb[tid] = bih[row] + bhh[row];
    }
    zero_h_tile(g_h1b[0], mb, b0, tid);

    unsigned lsense = 0;
    grid_barrier(&lsense);

    const float4* Ai4 = (const float4*)(g_A1i + (size_t)(mb * 4 + wm) * 16384);
    const float4* Ah4 = (const float4*)(g_A1h + (size_t)(mb * 4 + wm) * 16384);
    const int bg0 = b0 + wn * 16 + gi;
    const int bg1 = bg0 + 8;
    const int jj = tid >> 4, bl = tid & 15;
    float cst[2] = {0.f, 0.f};

    for (int t = 0; t < TT; ++t) {
        const int rb = t & 1, wb = rb ^ 1;

        float acc[2][3][4];
#pragma unroll
        for (int nt = 0; nt < 2; ++nt)
#pragma unroll
            for (int s = 0; s < 3; ++s)
#pragma unroll
                for (int i = 0; i < 4; ++i) acc[nt][s][i] = 0.f;

        // input part: y0[t] (slot t+1)
        mma_sweep(acc, Ai4, g_y0b + (size_t)(t + 1) * BSLOT, lane, ti, bg0, bg1);
        // recurrent part: h1[t-1]
        mma_sweep(acc, Ah4, g_h1b[rb], lane, ti, bg0, bg1);

        sts_D(gsm, acc, wm, wn, gi, ti);
        __syncthreads();

#pragma unroll
        for (int u = 0; u < 2; ++u) {
            int b = bl + u * 16;
            float s0 = cb[jj * 4 + 0] + gsm[(jj * 4 + 0) * 33 + b];
            float s1 = cb[jj * 4 + 1] + gsm[(jj * 4 + 1) * 33 + b];
            float s2 = cb[jj * 4 + 2] + gsm[(jj * 4 + 2) * 33 + b];
            float s3 = cb[jj * 4 + 3] + gsm[(jj * 4 + 3) * 33 + b];
            cst[u] = sigf(s1) * cst[u] + sigf(s0) * tanhf(s2);
            float h = sigf(s3) * tanhf(cst[u]);
            float2 hs = split_tf32(h);
            hsm_hi[jj * 32 + b] = hs.x;
            hsm_lo[jj * 32 + b] = hs.y;
        }
        __syncthreads();
        store_h_tile(g_h1b[wb], hsm_hi, hsm_lo, mb, b0, tid);
        grid_barrier(&lsense);
    }
    grid_barrier(&lsense);                           // even; final h in g_h1b[0]
}

// ---------------- final linear ----------------
extern "C" __global__ void final_linear(const float* __restrict__ lin_w,
                                        const float* __restrict__ lin_b,
                                        float* __restrict__ out)
{
    __shared__ float wrow[HH];
    int o = blockIdx.x, b = threadIdx.x;
    for (int k = b; k < HH; k += 128) wrow[k] = lin_w[o * HH + k];
    __syncthreads();
    float acc = 0.f;
#pragma unroll 4
    for (int j = 0; j < HH; ++j) {
        int kt = j >> 3, p = j & 3, s = (j >> 2) & 1;
        size_t base = ((size_t)(kt * 128 + b) << 4) + (p << 2);
        float h = g_h1b[0][base + s] + g_h1b[0][base + 2 + s];
        acc = fmaf(h, wrow[j], acc);
    }
    out[b * OOUT + o] = acc + lin_b[o];
}

// ---------------- launch ----------------
extern "C" void kernel_launch(void* const* d_in, const int* in_sizes, int n_in,
                              void* d_out, int out_size)
{
    const float* x     = (const float*)d_in[0];
    const float* wih0  = (const float*)d_in[1];
    const float* whh0  = (const float*)d_in[2];
    const float* bih0  = (const float*)d_in[3];
    const float* bhh0  = (const float*)d_in[4];
    const float* wih1  = (const float*)d_in[5];
    const float* whh1  = (const float*)d_in[6];
    const float* bih1  = (const float*)d_in[7];
    const float* bhh1  = (const float*)d_in[8];
    const float* lin_w = (const float*)d_in[9];
    const float* lin_b = (const float*)d_in[10];

    prep_weights<<<(3 * 2048 * 512 + 255) / 256, 256>>>(whh0, wih1, whh1);
    lstm_l0<<<NBLK, NTHR>>>(x, wih0, bih0, bhh0);
    lstm_l1<<<NBLK, NTHR>>>(bih1, bhh1);
    final_linear<<<OOUT, 128>>>(lin_w, lin_b, (float*)d_out);
}

// round 5
// speedup vs baseline: 2.2476x; 1.2251x over previous
#include <cuda_runtime.h>
#include <cstdint>

#define BB   128
#define TT   1024
#define HH   512
#define IIN  17
#define OOUT 17
#define NBLK 128
#define NTHR 256

// B'' slot: 64 k-tiles x 128 batch x 16 floats {hi(k),hi(k+4),lo(k),lo(k+4)}
#define BSLOT (64 * 128 * 16)          // 131072 floats = 512KB
// A' matrix: 128 m-tiles x 64 k-tiles x 32 lanes x 8 floats {hi[4], lo[4]}
#define AMAT  (128 * 64 * 32 * 8)      // 8MB

// ---------------- device scratch ----------------
__device__ float g_A0 [AMAT];                      // whh0 split, frag order
__device__ float g_A1i[AMAT];                      // wih1 split
__device__ float g_A1h[AMAT];                      // whh1 split
__device__ float g_y0b[(size_t)(TT + 1) * BSLOT];  // layer0 h rolling buffer
__device__ float g_h1b[(size_t)(TT + 1) * BSLOT];  // layer1 h rolling buffer
__device__ float g_proj1[(size_t)TT * 2048 * BB];  // precomputed wih1 @ y0, 1GB

__device__ unsigned          g_cnt[8][32];         // padded group counters
__device__ unsigned          g_root = 0;
__device__ volatile unsigned g_sense = 0;
__device__ unsigned          g_done = 0;

// ---------------- two-level grid barrier (monotonic) ----------------
__device__ __forceinline__ void grid_barrier(unsigned& tgt)
{
    __syncthreads();
    if (threadIdx.x == 0) {
        ++tgt;
        __threadfence();
        unsigned gid = blockIdx.x & 7;
        if ((atomicAdd(&g_cnt[gid][0], 1u) & 15u) == 15u) {
            __threadfence();
            if ((atomicAdd(&g_root, 1u) & 7u) == 7u) {
                __threadfence();
                atomicAdd((unsigned*)&g_sense, 1u);
            }
        }
        while (g_sense < tgt) { }
        __threadfence();
    }
    __syncthreads();
}

// Call after the last grid_barrier of a kernel: returns global state to zero.
__device__ __forceinline__ void barrier_epilogue()
{
    if (threadIdx.x == 0) {
        __threadfence();
        atomicAdd(&g_done, 1u);
        if (blockIdx.x == 0) {
            while (*(volatile unsigned*)&g_done < NBLK) { }
            for (int i = 0; i < 8; ++i) g_cnt[i][0] = 0;
            g_root = 0;
            g_done = 0;
            g_sense = 0;
            __threadfence();
        }
    }
}

// ---------------- tf32 helpers ----------------
__device__ __forceinline__ float2 split_tf32(float w)
{
    uint32_t hb;
    asm("cvt.rna.tf32.f32 %0, %1;" : "=r"(hb) : "f"(w));
    float hi = __uint_as_float(hb);
    float r = w - hi;
    uint32_t lb;
    asm("cvt.rna.tf32.f32 %0, %1;" : "=r"(lb) : "f"(r));
    return make_float2(hi, __uint_as_float(lb));
}

__device__ __forceinline__ void mma_tf32(float c[4], const float4& a,
                                         float b0, float b1)
{
    asm("mma.sync.aligned.m16n8k8.row.col.f32.tf32.tf32.f32 "
        "{%0,%1,%2,%3}, {%4,%5,%6,%7}, {%8,%9}, {%0,%1,%2,%3};"
        : "+f"(c[0]), "+f"(c[1]), "+f"(c[2]), "+f"(c[3])
        : "r"(__float_as_uint(a.x)), "r"(__float_as_uint(a.y)),
          "r"(__float_as_uint(a.z)), "r"(__float_as_uint(a.w)),
          "r"(__float_as_uint(b0)), "r"(__float_as_uint(b1)));
}

__device__ __forceinline__ float sigf(float v) { return 1.f / (1.f + expf(-v)); }

// ---------------- weight prep: split + fragment reorder ----------------
extern "C" __global__ void prep_weights(const float* __restrict__ whh0,
                                        const float* __restrict__ wih1,
                                        const float* __restrict__ whh1)
{
    const int ME = 2048 * 512;
    int idx = blockIdx.x * blockDim.x + threadIdx.x;
    if (idx >= 3 * ME) return;
    int mat = idx / ME, e = idx % ME;
    int mp = e >> 9, k = e & 511;
    int cell = mp >> 2, g = mp & 3;
    const float* W = (mat == 0) ? whh0 : (mat == 1) ? wih1 : whh1;
    float2 s = split_tf32(W[(size_t)(g * HH + cell) * HH + k]);
    int mt = mp >> 4, rl = mp & 15;
    int kt = k >> 3,  cl = k & 7;
    int a = (rl >> 3) | ((cl >> 2) << 1);
    int lane = (rl & 7) * 4 + (cl & 3);
    float* dst = (mat == 0) ? g_A0 : (mat == 1) ? g_A1i : g_A1h;
    size_t base = (((size_t)mt * 64 + kt) * 32 + lane) * 8;
    dst[base + a]     = s.x;
    dst[base + 4 + a] = s.y;
}

// ================= recurrent kernel (both layers) =================
// grid 128 = 64 mb x 2 nb.  Block: 8 cells x 64 batches; A slice (128KB) in smem.
#define SMEM_FLOATS (32768 + 32*65 + 2*8*64 + 32 + 32*IIN + 64*IIN)
#define SMEM_BYTES  (SMEM_FLOATS * 4)

template<bool IS_L0>
__global__ void __launch_bounds__(NTHR, 1)
lstm_rec(const float* __restrict__ x,         // L0 only
         const float* __restrict__ wih,       // L0 only
         const float* __restrict__ bih, const float* __restrict__ bhh)
{
    extern __shared__ float sm[];
    float*  ahi = sm;                          // 16384
    float*  alo = sm + 16384;                  // 16384
    float*  gsm = sm + 32768;                  // 32*65
    float*  hsm_hi = gsm + 32 * 65;            // 8*64
    float*  hsm_lo = hsm_hi + 8 * 64;          // 8*64
    float*  cb  = hsm_lo + 8 * 64;             // 32
    float*  Wi  = cb + 32;                     // 32*17
    float*  Xs  = Wi + 32 * IIN;               // 64*17

    const float* Afrag = IS_L0 ? g_A0 : g_A1h;
    float*       hbuf  = IS_L0 ? g_y0b : g_h1b;

    const int tid = threadIdx.x;
    const int lane = tid & 31, wid = tid >> 5;
    const int wm = wid & 1, wn = wid >> 1;          // 2 m-tiles x 4 n-groups
    const int gi = lane >> 2, ti = lane & 3;
    const int mb = blockIdx.x >> 1, nb = blockIdx.x & 1;
    const int b0 = nb * 64;
    const int jj = wid, bl = lane;                  // epilogue: cell jj, batch bl(+32)

    // ---- prologue ----
    {   // A slice -> smem, de-interleaved hi/lo
        const float4* src4 = (const float4*)(Afrag + (size_t)mb * 32768);
        float4* ahi4 = (float4*)ahi;
        float4* alo4 = (float4*)alo;
        for (int i = tid; i < 4096; i += NTHR) {
            ahi4[i] = src4[2 * i];
            alo4[i] = src4[2 * i + 1];
        }
    }
    if (tid < 32) {
        int cell = mb * 8 + (tid >> 2), g = tid & 3;
        cb[tid] = bih[g * HH + cell] + bhh[g * HH + cell];
    }
    if (IS_L0) {
        for (int idx = tid; idx < 32 * IIN; idx += NTHR) {
            int r = idx / IIN, k = idx - r * IIN;
            int cell = mb * 8 + (r >> 2), g = r & 3;
            Wi[idx] = wih[(size_t)(g * HH + cell) * IIN + k];
        }
    }
    // zero slot 0 of our tile
    for (int f = tid; f < 1024; f += NTHR) {
        int b = f >> 4, r = f & 15;
        __stcg(&hbuf[((size_t)(mb * 128 + b0 + b) << 4) + r], 0.f);
    }

    unsigned tgt = 0;
    grid_barrier(tgt);

    float cst[2] = {0.f, 0.f};
    const int bgA = b0 + wn * 16 + gi;
    const int bgB = bgA + 8;
    const float4* ahi4 = (const float4*)ahi + wm * 64 * 32;
    const float4* alo4 = (const float4*)alo + wm * 64 * 32;

    for (int t = 0; t < TT; ++t) {
        float pr[2][4];
        if (IS_L0) {
            for (int idx = tid; idx < 64 * IIN; idx += NTHR) {
                int r = idx / IIN, k = idx - r * IIN;
                Xs[idx] = x[((size_t)(b0 + r) * TT + t) * IIN + k];
            }
        } else {
            // prefetch proj1 tile into regs (hidden behind mma sweep)
            const float* pp = g_proj1 + ((size_t)t * 2048 + mb * 32 + jj * 4) * BB + b0 + bl;
#pragma unroll
            for (int g = 0; g < 4; ++g) {
                pr[0][g] = __ldcg(pp + g * BB);
                pr[1][g] = __ldcg(pp + g * BB + 32);
            }
        }

        // ---- mma sweep: K=512, A in smem, B via L1 ----
        float acc0[4] = {0.f, 0.f, 0.f, 0.f};
        float acc1[4] = {0.f, 0.f, 0.f, 0.f};
        const float4* Bt = (const float4*)(hbuf + (size_t)t * BSLOT);
#pragma unroll 4
        for (int kt = 0; kt < 64; ++kt) {
            float4 ah = ahi4[kt * 32 + lane];
            float4 al = alo4[kt * 32 + lane];
            float4 bv0 = Bt[(size_t)(kt * 128 + bgA) * 4 + ti];
            float4 bv1 = Bt[(size_t)(kt * 128 + bgB) * 4 + ti];
            mma_tf32(acc0, ah, bv0.x, bv0.y);
            mma_tf32(acc0, ah, bv0.z, bv0.w);
            mma_tf32(acc0, al, bv0.x, bv0.y);
            mma_tf32(acc1, ah, bv1.x, bv1.y);
            mma_tf32(acc1, ah, bv1.z, bv1.w);
            mma_tf32(acc1, al, bv1.x, bv1.y);
        }

        // ---- D -> smem ----
        {
            int r0 = wm * 16 + gi;
            int col = wn * 16 + 2 * ti;
            gsm[r0 * 65 + col]           = acc0[0];
            gsm[r0 * 65 + col + 1]       = acc0[1];
            gsm[(r0 + 8) * 65 + col]     = acc0[2];
            gsm[(r0 + 8) * 65 + col + 1] = acc0[3];
            gsm[r0 * 65 + col + 8]           = acc1[0];
            gsm[r0 * 65 + col + 9]           = acc1[1];
            gsm[(r0 + 8) * 65 + col + 8]     = acc1[2];
            gsm[(r0 + 8) * 65 + col + 9]     = acc1[3];
        }
        __syncthreads();

        // ---- cell update: thread owns cell jj, batches bl, bl+32 ----
#pragma unroll
        for (int u = 0; u < 2; ++u) {
            int b = bl + u * 32;
            float s0 = cb[jj * 4 + 0] + gsm[(jj * 4 + 0) * 65 + b];
            float s1 = cb[jj * 4 + 1] + gsm[(jj * 4 + 1) * 65 + b];
            float s2 = cb[jj * 4 + 2] + gsm[(jj * 4 + 2) * 65 + b];
            float s3 = cb[jj * 4 + 3] + gsm[(jj * 4 + 3) * 65 + b];
            if (IS_L0) {
#pragma unroll
                for (int k = 0; k < IIN; ++k) {
                    float xv = Xs[b * IIN + k];
                    s0 = fmaf(Wi[(jj * 4 + 0) * IIN + k], xv, s0);
                    s1 = fmaf(Wi[(jj * 4 + 1) * IIN + k], xv, s1);
                    s2 = fmaf(Wi[(jj * 4 + 2) * IIN + k], xv, s2);
                    s3 = fmaf(Wi[(jj * 4 + 3) * IIN + k], xv, s3);
                }
            } else {
                s0 += pr[u][0]; s1 += pr[u][1]; s2 += pr[u][2]; s3 += pr[u][3];
            }
            cst[u] = sigf(s1) * cst[u] + sigf(s0) * tanhf(s2);
            float h = sigf(s3) * tanhf(cst[u]);
            float2 hs = split_tf32(h);
            hsm_hi[jj * 64 + b] = hs.x;
            hsm_lo[jj * 64 + b] = hs.y;
        }
        __syncthreads();

        // ---- publish h (slot t+1), coalesced ----
        {
            float* dst = hbuf + (size_t)(t + 1) * BSLOT;
#pragma unroll
            for (int f = tid; f < 1024; f += NTHR) {
                int b = f >> 4, rem = f & 15, p = rem >> 2, q = rem & 3;
                int j = p + (q & 1) * 4;
                float v = (q < 2) ? hsm_hi[j * 64 + b] : hsm_lo[j * 64 + b];
                __stcg(&dst[((size_t)(mb * 128 + b0 + b) << 4) + (p << 2) + q], v);
            }
        }
        grid_barrier(tgt);
    }
    barrier_epilogue();
}

// ================= proj1 GEMM: proj1[t][m'][b] = wih1' @ y0[t] =================
// grid 16384 = 16 m-chunks x 1024 t; block m128 x n128; 8 warps (wm2 x wn4).
extern "C" __global__ void __launch_bounds__(NTHR, 1)
proj1_gemm()
{
    const int tid = threadIdx.x;
    const int lane = tid & 31, wid = tid >> 5;
    const int wm = wid & 1, wn = wid >> 1;
    const int gi = lane >> 2, ti = lane & 3;
    const int mc = blockIdx.x & 15;
    const int t  = blockIdx.x >> 4;

    float acc[4][4][4];
#pragma unroll
    for (int a = 0; a < 4; ++a)
#pragma unroll
        for (int b = 0; b < 4; ++b)
#pragma unroll
            for (int c = 0; c < 4; ++c) acc[a][b][c] = 0.f;

    const float4* A4 = (const float4*)g_A1i;
    const float4* B4 = (const float4*)(g_y0b + (size_t)(t + 1) * BSLOT);
    const int mt0 = mc * 8 + wm * 4;

#pragma unroll 2
    for (int kt = 0; kt < 64; ++kt) {
        float4 ah[4], al[4], bv[4];
#pragma unroll
        for (int mt = 0; mt < 4; ++mt) {
            size_t base = ((size_t)((mt0 + mt) * 64 + kt) * 32 + lane) * 2;
            ah[mt] = A4[base];
            al[mt] = A4[base + 1];
        }
#pragma unroll
        for (int nt = 0; nt < 4; ++nt) {
            int bg = wn * 32 + nt * 8 + gi;
            bv[nt] = B4[(size_t)(kt * 128 + bg) * 4 + ti];
        }
#pragma unroll
        for (int mt = 0; mt < 4; ++mt)
#pragma unroll
            for (int nt = 0; nt < 4; ++nt) {
                mma_tf32(acc[mt][nt], ah[mt], bv[nt].x, bv[nt].y);
                mma_tf32(acc[mt][nt], ah[mt], bv[nt].z, bv[nt].w);
                mma_tf32(acc[mt][nt], al[mt], bv[nt].x, bv[nt].y);
            }
    }

    // store
#pragma unroll
    for (int mt = 0; mt < 4; ++mt)
#pragma unroll
        for (int nt = 0; nt < 4; ++nt) {
            int r = (mt0 + mt) * 16 + gi;
            int b = wn * 32 + nt * 8 + 2 * ti;
            float* p0 = g_proj1 + ((size_t)t * 2048 + r) * BB + b;
            p0[0] = acc[mt][nt][0];
            p0[1] = acc[mt][nt][1];
            float* p1 = p0 + 8 * BB;
            p1[0] = acc[mt][nt][2];
            p1[1] = acc[mt][nt][3];
        }
}

// ---------------- final linear ----------------
extern "C" __global__ void final_linear(const float* __restrict__ lin_w,
                                        const float* __restrict__ lin_b,
                                        float* __restrict__ out)
{
    __shared__ float wrow[HH];
    int o = blockIdx.x, b = threadIdx.x;
    for (int k = b; k < HH; k += 128) wrow[k] = lin_w[o * HH + k];
    __syncthreads();
    const float* hb = g_h1b + (size_t)TT * BSLOT;
    float acc = 0.f;
#pragma unroll 4
    for (int j = 0; j < HH; ++j) {
        int kt = j >> 3, p = j & 3, s = (j >> 2) & 1;
        size_t base = ((size_t)(kt * 128 + b) << 4) + (p << 2);
        float h = hb[base + s] + hb[base + 2 + s];
        acc = fmaf(h, wrow[j], acc);
    }
    out[b * OOUT + o] = acc + lin_b[o];
}

// ---------------- launch ----------------
extern "C" void kernel_launch(void* const* d_in, const int* in_sizes, int n_in,
                              void* d_out, int out_size)
{
    const float* x     = (const float*)d_in[0];
    const float* wih0  = (const float*)d_in[1];
    const float* whh0  = (const float*)d_in[2];
    const float* bih0  = (const float*)d_in[3];
    const float* bhh0  = (const float*)d_in[4];
    const float* wih1  = (const float*)d_in[5];
    const float* whh1  = (const float*)d_in[6];
    const float* bih1  = (const float*)d_in[7];
    const float* bhh1  = (const float*)d_in[8];
    const float* lin_w = (const float*)d_in[9];
    const float* lin_b = (const float*)d_in[10];

    cudaFuncSetAttribute(lstm_rec<true>,  cudaFuncAttributeMaxDynamicSharedMemorySize, SMEM_BYTES);
    cudaFuncSetAttribute(lstm_rec<false>, cudaFuncAttributeMaxDynamicSharedMemorySize, SMEM_BYTES);

    prep_weights<<<(3 * 2048 * 512 + 255) / 256, 256>>>(whh0, wih1, whh1);
    lstm_rec<true><<<NBLK, NTHR, SMEM_BYTES>>>(x, wih0, bih0, bhh0);
    proj1_gemm<<<16384, NTHR>>>();
    lstm_rec<false><<<NBLK, NTHR, SMEM_BYTES>>>(nullptr, nullptr, bih1, bhh1);
    final_linear<<<OOUT, 128>>>(lin_w, lin_b, (float*)d_out);
}

// round 6
// speedup vs baseline: 2.3880x; 1.0625x over previous
#include <cuda_runtime.h>
#include <cstdint>

#define BB   128
#define TT   1024
#define HH   512
#define IIN  17
#define OOUT 17
#define NBLK 128
#define NTHR 512

// B'' slot: 64 k-tiles x 128 batch x 16 floats {hi(k),hi(k+4),lo(k),lo(k+4)}
#define BSLOT (64 * 128 * 16)          // 131072 floats = 512KB
// A' matrix: 128 m-tiles x 64 k-tiles x 32 lanes x 8 floats {hi[4], lo[4]}
#define AMAT  (128 * 64 * 32 * 8)      // 8MB

// ---------------- device scratch ----------------
__device__ float g_A0 [AMAT];
__device__ float g_A1i[AMAT];
__device__ float g_A1h[AMAT];
__device__ float g_y0b[(size_t)(TT + 1) * BSLOT];
__device__ float g_h1b[(size_t)(TT + 1) * BSLOT];
__device__ float g_proj1[(size_t)TT * 2048 * BB];

__device__ unsigned          g_cnt[8][32];
__device__ unsigned          g_root = 0;
__device__ volatile unsigned g_sense = 0;
__device__ unsigned          g_done = 0;

// ---------------- split-phase grid barrier (monotonic counters) ----------------
__device__ __forceinline__ void bar_arrive()
{
    __threadfence();
    unsigned gid = blockIdx.x & 7;
    if ((atomicAdd(&g_cnt[gid][0], 1u) & 15u) == 15u) {
        __threadfence();
        if ((atomicAdd(&g_root, 1u) & 7u) == 7u) {
            __threadfence();
            atomicAdd((unsigned*)&g_sense, 1u);
        }
    }
}
__device__ __forceinline__ void bar_wait(unsigned tgt)
{
    while (g_sense < tgt) { }
    __threadfence();
}
// after final arrive: reset all barrier state for next kernel / next graph replay
__device__ __forceinline__ void barrier_epilogue()
{
    if (threadIdx.x == 0) {
        __threadfence();
        atomicAdd(&g_done, 1u);
        if (blockIdx.x == 0) {
            while (*(volatile unsigned*)&g_done < NBLK) { }
            for (int i = 0; i < 8; ++i) g_cnt[i][0] = 0;
            g_root = 0;
            g_done = 0;
            g_sense = 0;
            __threadfence();
        }
    }
}

// ---------------- tf32 helpers ----------------
__device__ __forceinline__ float2 split_tf32(float w)
{
    uint32_t hb;
    asm("cvt.rna.tf32.f32 %0, %1;" : "=r"(hb) : "f"(w));
    float hi = __uint_as_float(hb);
    float r = w - hi;
    uint32_t lb;
    asm("cvt.rna.tf32.f32 %0, %1;" : "=r"(lb) : "f"(r));
    return make_float2(hi, __uint_as_float(lb));
}

__device__ __forceinline__ void mma_tf32(float c[4], const float4& a,
                                         float b0, float b1)
{
    asm("mma.sync.aligned.m16n8k8.row.col.f32.tf32.tf32.f32 "
        "{%0,%1,%2,%3}, {%4,%5,%6,%7}, {%8,%9}, {%0,%1,%2,%3};"
        : "+f"(c[0]), "+f"(c[1]), "+f"(c[2]), "+f"(c[3])
        : "r"(__float_as_uint(a.x)), "r"(__float_as_uint(a.y)),
          "r"(__float_as_uint(a.z)), "r"(__float_as_uint(a.w)),
          "r"(__float_as_uint(b0)), "r"(__float_as_uint(b1)));
}

__device__ __forceinline__ float sigf(float v) { return 1.f / (1.f + expf(-v)); }

// ---------------- weight prep: split + fragment reorder ----------------
extern "C" __global__ void prep_weights(const float* __restrict__ whh0,
                                        const float* __restrict__ wih1,
                                        const float* __restrict__ whh1)
{
    const int ME = 2048 * 512;
    int idx = blockIdx.x * blockDim.x + threadIdx.x;
    if (idx >= 3 * ME) return;
    int mat = idx / ME, e = idx % ME;
    int mp = e >> 9, k = e & 511;
    int cell = mp >> 2, g = mp & 3;
    const float* W = (mat == 0) ? whh0 : (mat == 1) ? wih1 : whh1;
    float2 s = split_tf32(W[(size_t)(g * HH + cell) * HH + k]);
    int mt = mp >> 4, rl = mp & 15;
    int kt = k >> 3,  cl = k & 7;
    int a = (rl >> 3) | ((cl >> 2) << 1);
    int lane = (rl & 7) * 4 + (cl & 3);
    float* dst = (mat == 0) ? g_A0 : (mat == 1) ? g_A1i : g_A1h;
    size_t base = (((size_t)mt * 64 + kt) * 32 + lane) * 8;
    dst[base + a]     = s.x;
    dst[base + 4 + a] = s.y;
}

// ================= recurrent kernel (both layers) =================
// grid 128 = 64 mb x 2 nb.  Block: 8 cells (32 gate rows) x 64 batches.
// 16 warps: wm (2 m-tiles) x wn (8 n-tiles of 8 batches).
#define SMEM_FLOATS (32768 + 32*65 + 2*8*64 + 32 + 64*IIN)
#define SMEM_BYTES  (SMEM_FLOATS * 4)

template<bool IS_L0>
__global__ void __launch_bounds__(NTHR, 1)
lstm_rec(const float* __restrict__ x,
         const float* __restrict__ wih,
         const float* __restrict__ bih, const float* __restrict__ bhh)
{
    extern __shared__ float sm[];
    float*  ahi = sm;                          // 16384
    float*  alo = sm + 16384;                  // 16384
    float*  gsm = sm + 32768;                  // 32*65
    float*  hsm_hi = gsm + 32 * 65;            // 8*64
    float*  hsm_lo = hsm_hi + 8 * 64;          // 8*64
    float*  cb  = hsm_lo + 8 * 64;             // 32
    float*  Xs  = cb + 32;                     // 64*17 (L0 only)

    const float* Afrag = IS_L0 ? g_A0 : g_A1h;
    float*       hbuf  = IS_L0 ? g_y0b : g_h1b;

    const int tid = threadIdx.x;
    const int lane = tid & 31, wid = tid >> 5;
    const int wm = wid & 1, wn = wid >> 1;          // 2 m-tiles x 8 n-tiles
    const int gi = lane >> 2, ti = lane & 3;
    const int mb = blockIdx.x >> 1, nb = blockIdx.x & 1;
    const int b0 = nb * 64;
    const int jj = tid >> 6, bl = tid & 63;         // epilogue: cell jj, batch bl

    // ---- prologue ----
    {
        const float4* src4 = (const float4*)(Afrag + (size_t)mb * 32768);
        float4* ahi4 = (float4*)ahi;
        float4* alo4 = (float4*)alo;
        for (int i = tid; i < 4096; i += NTHR) {
            ahi4[i] = src4[2 * i];
            alo4[i] = src4[2 * i + 1];
        }
    }
    if (tid < 32) {
        int cell = mb * 8 + (tid >> 2), g = tid & 3;
        cb[tid] = bih[g * HH + cell] + bhh[g * HH + cell];
    }
    // zero slot 0 of our tile
    for (int f = tid; f < 1024; f += NTHR) {
        int b = f >> 4, r = f & 15;
        __stcg(&hbuf[((size_t)(mb * 128 + b0 + b) << 4) + r], 0.f);
    }
    __syncthreads();
    if (tid == 0) bar_arrive();                 // round 1: slot-0 published

    float cst = 0.f;
    const float Wi0 = 0.f; (void)Wi0;
    // L0: stash this thread's 4x17 wih rows in registers? keep smem Xs + global wih in L1.
    const int bg = b0 + wn * 8 + gi;
    const float4* ahi4 = (const float4*)ahi + wm * 64 * 32;
    const float4* alo4 = (const float4*)alo + wm * 64 * 32;

    unsigned tgt = 0;

    for (int t = 0; t < TT; ++t) {
        float pr[4];
        if (IS_L0) {
            for (int idx = tid; idx < 64 * IIN; idx += NTHR) {
                int r = idx / IIN, k = idx - r * IIN;
                Xs[idx] = x[((size_t)(b0 + r) * TT + t) * IIN + k];
            }
        } else {
            const float* pp = g_proj1 + ((size_t)t * 2048 + mb * 32 + jj * 4) * BB + b0 + bl;
#pragma unroll
            for (int g = 0; g < 4; ++g) pr[g] = __ldcg(pp + g * BB);
        }

        ++tgt;
        if (tid == 0) bar_wait(tgt);            // h slot t ready grid-wide
        __syncthreads();

        // ---- mma sweep: K=512, 3 independent accumulator chains ----
        float accM[4]  = {0.f, 0.f, 0.f, 0.f};
        float accC1[4] = {0.f, 0.f, 0.f, 0.f};
        float accC2[4] = {0.f, 0.f, 0.f, 0.f};
        const float4* Bt = (const float4*)(hbuf + (size_t)t * BSLOT);
#pragma unroll 4
        for (int kt = 0; kt < 64; ++kt) {
            float4 ah = ahi4[kt * 32 + lane];
            float4 al = alo4[kt * 32 + lane];
            float4 bv = Bt[(size_t)(kt * 128 + bg) * 4 + ti];
            mma_tf32(accM,  ah, bv.x, bv.y);    // hi*hi
            mma_tf32(accC1, ah, bv.z, bv.w);    // hi*lo
            mma_tf32(accC2, al, bv.x, bv.y);    // lo*hi
        }

        // ---- D -> smem ----
        {
            int r0 = wm * 16 + gi;
            int col = wn * 8 + 2 * ti;
            gsm[r0 * 65 + col]           = accM[0] + accC1[0] + accC2[0];
            gsm[r0 * 65 + col + 1]       = accM[1] + accC1[1] + accC2[1];
            gsm[(r0 + 8) * 65 + col]     = accM[2] + accC1[2] + accC2[2];
            gsm[(r0 + 8) * 65 + col + 1] = accM[3] + accC1[3] + accC2[3];
        }
        __syncthreads();

        // ---- cell update: thread owns (cell jj, batch bl) ----
        {
            float s0 = cb[jj * 4 + 0] + gsm[(jj * 4 + 0) * 65 + bl];
            float s1 = cb[jj * 4 + 1] + gsm[(jj * 4 + 1) * 65 + bl];
            float s2 = cb[jj * 4 + 2] + gsm[(jj * 4 + 2) * 65 + bl];
            float s3 = cb[jj * 4 + 3] + gsm[(jj * 4 + 3) * 65 + bl];
            if (IS_L0) {
                const float* wr = wih + (size_t)(mb * 8 + jj) * IIN;   // gate 0 row
#pragma unroll
                for (int k = 0; k < IIN; ++k) {
                    float xv = Xs[bl * IIN + k];
                    s0 = fmaf(__ldg(wr + 0 * HH * IIN + k), xv, s0);
                    s1 = fmaf(__ldg(wr + 1 * HH * IIN + k), xv, s1);
                    s2 = fmaf(__ldg(wr + 2 * HH * IIN + k), xv, s2);
                    s3 = fmaf(__ldg(wr + 3 * HH * IIN + k), xv, s3);
                }
            } else {
                s0 += pr[0]; s1 += pr[1]; s2 += pr[2]; s3 += pr[3];
            }
            cst = sigf(s1) * cst + sigf(s0) * tanhf(s2);
            float h = sigf(s3) * tanhf(cst);
            float2 hs = split_tf32(h);
            hsm_hi[jj * 64 + bl] = hs.x;
            hsm_lo[jj * 64 + bl] = hs.y;
        }
        __syncthreads();

        // ---- publish h (slot t+1), coalesced ----
        {
            float* dst = hbuf + (size_t)(t + 1) * BSLOT;
#pragma unroll
            for (int u = 0; u < 2; ++u) {
                int f = tid + u * NTHR;
                int b = f >> 4, rem = f & 15, p = rem >> 2, q = rem & 3;
                int j = p + (q & 1) * 4;
                float v = (q < 2) ? hsm_hi[j * 64 + b] : hsm_lo[j * 64 + b];
                __stcg(&dst[((size_t)(mb * 128 + b0 + b) << 4) + (p << 2) + q], v);
            }
        }
        __syncthreads();
        if (tid == 0) bar_arrive();
    }
    barrier_epilogue();
}

// ================= proj1 GEMM: proj1[t][m'][b] = wih1' @ y0[t] =================
extern "C" __global__ void __launch_bounds__(256, 1)
proj1_gemm()
{
    const int tid = threadIdx.x;
    const int lane = tid & 31, wid = tid >> 5;
    const int wm = wid & 1, wn = wid >> 1;
    const int gi = lane >> 2, ti = lane & 3;
    const int mc = blockIdx.x & 15;
    const int t  = blockIdx.x >> 4;

    float acc[4][4][4];
#pragma unroll
    for (int a = 0; a < 4; ++a)
#pragma unroll
        for (int b = 0; b < 4; ++b)
#pragma unroll
            for (int c = 0; c < 4; ++c) acc[a][b][c] = 0.f;

    const float4* A4 = (const float4*)g_A1i;
    const float4* B4 = (const float4*)(g_y0b + (size_t)(t + 1) * BSLOT);
    const int mt0 = mc * 8 + wm * 4;

#pragma unroll 2
    for (int kt = 0; kt < 64; ++kt) {
        float4 ah[4], al[4], bv[4];
#pragma unroll
        for (int mt = 0; mt < 4; ++mt) {
            size_t base = ((size_t)((mt0 + mt) * 64 + kt) * 32 + lane) * 2;
            ah[mt] = A4[base];
            al[mt] = A4[base + 1];
        }
#pragma unroll
        for (int nt = 0; nt < 4; ++nt) {
            int bg = wn * 32 + nt * 8 + gi;
            bv[nt] = B4[(size_t)(kt * 128 + bg) * 4 + ti];
        }
#pragma unroll
        for (int mt = 0; mt < 4; ++mt)
#pragma unroll
            for (int nt = 0; nt < 4; ++nt) {
                mma_tf32(acc[mt][nt], ah[mt], bv[nt].x, bv[nt].y);
                mma_tf32(acc[mt][nt], ah[mt], bv[nt].z, bv[nt].w);
                mma_tf32(acc[mt][nt], al[mt], bv[nt].x, bv[nt].y);
            }
    }

#pragma unroll
    for (int mt = 0; mt < 4; ++mt)
#pragma unroll
        for (int nt = 0; nt < 4; ++nt) {
            int r = (mt0 + mt) * 16 + gi;
            int b = wn * 32 + nt * 8 + 2 * ti;
            float* p0 = g_proj1 + ((size_t)t * 2048 + r) * BB + b;
            p0[0] = acc[mt][nt][0];
            p0[1] = acc[mt][nt][1];
            float* p1 = p0 + 8 * BB;
            p1[0] = acc[mt][nt][2];
            p1[1] = acc[mt][nt][3];
        }
}

// ---------------- final linear ----------------
extern "C" __global__ void final_linear(const float* __restrict__ lin_w,
                                        const float* __restrict__ lin_b,
                                        float* __restrict__ out)
{
    __shared__ float wrow[HH];
    int o = blockIdx.x, b = threadIdx.x;
    for (int k = b; k < HH; k += 128) wrow[k] = lin_w[o * HH + k];
    __syncthreads();
    const float* hb = g_h1b + (size_t)TT * BSLOT;
    float acc = 0.f;
#pragma unroll 4
    for (int j = 0; j < HH; ++j) {
        int kt = j >> 3, p = j & 3, s = (j >> 2) & 1;
        size_t base = ((size_t)(kt * 128 + b) << 4) + (p << 2);
        float h = hb[base + s] + hb[base + 2 + s];
        acc = fmaf(h, wrow[j], acc);
    }
    out[b * OOUT + o] = acc + lin_b[o];
}

// ---------------- launch ----------------
extern "C" void kernel_launch(void* const* d_in, const int* in_sizes, int n_in,
                              void* d_out, int out_size)
{
    const float* x     = (const float*)d_in[0];
    const float* wih0  = (const float*)d_in[1];
    const float* whh0  = (const float*)d_in[2];
    const float* bih0  = (const float*)d_in[3];
    const float* bhh0  = (const float*)d_in[4];
    const float* wih1  = (const float*)d_in[5];
    const float* whh1  = (const float*)d_in[6];
    const float* bih1  = (const float*)d_in[7];
    const float* bhh1  = (const float*)d_in[8];
    const float* lin_w = (const float*)d_in[9];
    const float* lin_b = (const float*)d_in[10];

    cudaFuncSetAttribute(lstm_rec<true>,  cudaFuncAttributeMaxDynamicSharedMemorySize, SMEM_BYTES);
    cudaFuncSetAttribute(lstm_rec<false>, cudaFuncAttributeMaxDynamicSharedMemorySize, SMEM_BYTES);

    prep_weights<<<(3 * 2048 * 512 + 255) / 256, 256>>>(whh0, wih1, whh1);
    lstm_rec<true><<<NBLK, NTHR, SMEM_BYTES>>>(x, wih0, bih0, bhh0);
    proj1_gemm<<<16384, 256>>>();
    lstm_rec<false><<<NBLK, NTHR, SMEM_BYTES>>>(nullptr, nullptr, bih1, bhh1);
    final_linear<<<OOUT, 128>>>(lin_w, lin_b, (float*)d_out);
}

// round 7
// speedup vs baseline: 2.6753x; 1.1203x over previous
#include <cuda_runtime.h>
#include <cstdint>

#define BB   128
#define TT   1024
#define HH   512
#define IIN  17
#define OOUT 17
#define NBLK 128
#define NTHR 512

// B'' slot: 64 k-tiles x 128 batch x 16 floats {hi(k),hi(k+4),lo(k),lo(k+4)}
#define BSLOT (64 * 128 * 16)          // 131072 floats = 512KB
// A' matrix: 128 m-tiles x 64 k-tiles x 32 lanes x 8 floats {hi[4], lo[4]}
#define AMAT  (128 * 64 * 32 * 8)      // 8MB

// ---------------- device scratch ----------------
__device__ float g_A0 [AMAT];
__device__ float g_A1i[AMAT];
__device__ float g_A1h[AMAT];
__device__ float g_y0b[(size_t)(TT + 1) * BSLOT];
__device__ float g_h1b[(size_t)(TT + 1) * BSLOT];
__device__ float g_proj1[(size_t)TT * 2048 * BB];

__device__ unsigned          g_cnt[8][32];
__device__ unsigned          g_root = 0;
__device__ volatile unsigned g_sense = 0;
__device__ unsigned          g_done = 0;

// ---------------- split-phase grid barrier (monotonic counters) ----------------
__device__ __forceinline__ void bar_arrive()
{
    __threadfence();
    unsigned gid = blockIdx.x & 7;
    if ((atomicAdd(&g_cnt[gid][0], 1u) & 15u) == 15u) {
        __threadfence();
        if ((atomicAdd(&g_root, 1u) & 7u) == 7u) {
            __threadfence();
            atomicAdd((unsigned*)&g_sense, 1u);
        }
    }
}
__device__ __forceinline__ void bar_wait(unsigned tgt)
{
    while (g_sense < tgt) { }
    __threadfence();
}
__device__ __forceinline__ void barrier_epilogue()
{
    if (threadIdx.x == 0) {
        __threadfence();
        atomicAdd(&g_done, 1u);
        if (blockIdx.x == 0) {
            while (*(volatile unsigned*)&g_done < NBLK) { }
            for (int i = 0; i < 8; ++i) g_cnt[i][0] = 0;
            g_root = 0;
            g_done = 0;
            g_sense = 0;
            __threadfence();
        }
    }
}

// ---------------- tf32 helpers ----------------
__device__ __forceinline__ float2 split_tf32(float w)
{
    uint32_t hb;
    asm("cvt.rna.tf32.f32 %0, %1;" : "=r"(hb) : "f"(w));
    float hi = __uint_as_float(hb);
    float r = w - hi;
    uint32_t lb;
    asm("cvt.rna.tf32.f32 %0, %1;" : "=r"(lb) : "f"(r));
    return make_float2(hi, __uint_as_float(lb));
}

__device__ __forceinline__ void mma_tf32(float c[4], const float4& a,
                                         float b0, float b1)
{
    asm("mma.sync.aligned.m16n8k8.row.col.f32.tf32.tf32.f32 "
        "{%0,%1,%2,%3}, {%4,%5,%6,%7}, {%8,%9}, {%0,%1,%2,%3};"
        : "+f"(c[0]), "+f"(c[1]), "+f"(c[2]), "+f"(c[3])
        : "r"(__float_as_uint(a.x)), "r"(__float_as_uint(a.y)),
          "r"(__float_as_uint(a.z)), "r"(__float_as_uint(a.w)),
          "r"(__float_as_uint(b0)), "r"(__float_as_uint(b1)));
}

__device__ __forceinline__ float sigf(float v) { return 1.f / (1.f + expf(-v)); }

// ---------------- weight prep: split + fragment reorder ----------------
extern "C" __global__ void prep_weights(const float* __restrict__ whh0,
                                        const float* __restrict__ wih1,
                                        const float* __restrict__ whh1)
{
    const int ME = 2048 * 512;
    int idx = blockIdx.x * blockDim.x + threadIdx.x;
    if (idx >= 3 * ME) return;
    int mat = idx / ME, e = idx % ME;
    int mp = e >> 9, k = e & 511;
    int cell = mp >> 2, g = mp & 3;
    const float* W = (mat == 0) ? whh0 : (mat == 1) ? wih1 : whh1;
    float2 s = split_tf32(W[(size_t)(g * HH + cell) * HH + k]);
    int mt = mp >> 4, rl = mp & 15;
    int kt = k >> 3,  cl = k & 7;
    int a = (rl >> 3) | ((cl >> 2) << 1);
    int lane = (rl & 7) * 4 + (cl & 3);
    float* dst = (mat == 0) ? g_A0 : (mat == 1) ? g_A1i : g_A1h;
    size_t base = (((size_t)mt * 64 + kt) * 32 + lane) * 8;
    dst[base + a]     = s.x;
    dst[base + 4 + a] = s.y;
}

// ================= recurrent kernel (both layers) =================
// grid 128 = 64 mb x 2 nb.  Block: 8 cells (32 gate rows) x 64 batches.
// 16 warps: wm(2 m-tiles) x wn(2 n-halves of 32) x wk(4 k-quarters of 16 kt).
// Warp tile: m16 x n32 (4 n-tiles), k-quarter. gsm has 4 k-split copies.
#define GSMC 2080                      // one gsm copy: 32 rows x 65
#define SMEM_FLOATS (32768 + 4*GSMC + 2*8*64 + 32 + 64*IIN)
#define SMEM_BYTES  (SMEM_FLOATS * 4)

template<bool IS_L0>
__global__ void __launch_bounds__(NTHR, 1)
lstm_rec(const float* __restrict__ x,
         const float* __restrict__ wih,
         const float* __restrict__ bih, const float* __restrict__ bhh)
{
    extern __shared__ float sm[];
    float*  ahi = sm;                          // 16384
    float*  alo = sm + 16384;                  // 16384
    float*  gsm = sm + 32768;                  // 4 * 2080
    float*  hsm_hi = gsm + 4 * GSMC;           // 8*64
    float*  hsm_lo = hsm_hi + 8 * 64;          // 8*64
    float*  cb  = hsm_lo + 8 * 64;             // 32
    float*  Xs  = cb + 32;                     // 64*17 (L0 only)

    const float* Afrag = IS_L0 ? g_A0 : g_A1h;
    float*       hbuf  = IS_L0 ? g_y0b : g_h1b;

    const int tid = threadIdx.x;
    const int lane = tid & 31, wid = tid >> 5;
    const int wm = wid & 1, wn = (wid >> 1) & 1, wk = wid >> 2;
    const int gi = lane >> 2, ti = lane & 3;
    const int mb = blockIdx.x >> 1, nb = blockIdx.x & 1;
    const int b0 = nb * 64;
    const int jj = tid >> 6, bl = tid & 63;         // epilogue: cell jj, batch bl

    // ---- prologue: A slice -> smem (hi/lo de-interleaved) ----
    {
        const float4* src4 = (const float4*)(Afrag + (size_t)mb * 32768);
        float4* ahi4 = (float4*)ahi;
        float4* alo4 = (float4*)alo;
        for (int i = tid; i < 4096; i += NTHR) {
            ahi4[i] = src4[2 * i];
            alo4[i] = src4[2 * i + 1];
        }
    }
    if (tid < 32) {
        int cell = mb * 8 + (tid >> 2), g = tid & 3;
        cb[tid] = bih[g * HH + cell] + bhh[g * HH + cell];
    }
    // zero slot 0 of our tile
    for (int f = tid; f < 1024; f += NTHR) {
        int b = f >> 4, r = f & 15;
        __stcg(&hbuf[((size_t)(mb * 128 + b0 + b) << 4) + r], 0.f);
    }
    __syncthreads();
    if (tid == 0) bar_arrive();                 // round 1: slot-0 published

    float cst = 0.f;
    const float4* ahw = (const float4*)ahi + (wm * 64 + wk * 16) * 32;
    const float4* alw = (const float4*)alo + (wm * 64 + wk * 16) * 32;

    unsigned tgt = 0;

    for (int t = 0; t < TT; ++t) {
        float pr[4];
        if (IS_L0) {
            for (int idx = tid; idx < 64 * IIN; idx += NTHR) {
                int r = idx / IIN, k = idx - r * IIN;
                Xs[idx] = x[((size_t)(b0 + r) * TT + t) * IIN + k];
            }
        } else {
            const float* pp = g_proj1 + ((size_t)t * 2048 + mb * 32 + jj * 4) * BB + b0 + bl;
#pragma unroll
            for (int g = 0; g < 4; ++g) pr[g] = __ldcg(pp + g * BB);
        }

        ++tgt;
        if (tid == 0) bar_wait(tgt);            // h slot t ready grid-wide
        __syncthreads();

        // ---- mma sweep: 16 kt, 4 n-tiles, 3 terms (12 chains) ----
        float acc[4][3][4];
#pragma unroll
        for (int nt = 0; nt < 4; ++nt)
#pragma unroll
            for (int s = 0; s < 3; ++s)
#pragma unroll
                for (int i = 0; i < 4; ++i) acc[nt][s][i] = 0.f;

        const float4* Bt = (const float4*)(hbuf + (size_t)t * BSLOT);
#pragma unroll 4
        for (int kt = 0; kt < 16; ++kt) {
            float4 ah = ahw[kt * 32 + lane];
            float4 al = alw[kt * 32 + lane];
            int ktg = wk * 16 + kt;
#pragma unroll
            for (int nt = 0; nt < 4; ++nt) {
                float4 bv = Bt[(size_t)(ktg * 128 + b0 + wn * 32 + nt * 8 + gi) * 4 + ti];
                mma_tf32(acc[nt][0], ah, bv.x, bv.y);   // hi*hi
                mma_tf32(acc[nt][1], ah, bv.z, bv.w);   // hi*lo
                mma_tf32(acc[nt][2], al, bv.x, bv.y);   // lo*hi
            }
        }

        // ---- D -> gsm copy [wk] ----
        {
            float* g = gsm + wk * GSMC;
            int r0 = wm * 16 + gi;
#pragma unroll
            for (int nt = 0; nt < 4; ++nt) {
                int col = wn * 32 + nt * 8 + 2 * ti;
                g[r0 * 65 + col]           = acc[nt][0][0] + acc[nt][1][0] + acc[nt][2][0];
                g[r0 * 65 + col + 1]       = acc[nt][0][1] + acc[nt][1][1] + acc[nt][2][1];
                g[(r0 + 8) * 65 + col]     = acc[nt][0][2] + acc[nt][1][2] + acc[nt][2][2];
                g[(r0 + 8) * 65 + col + 1] = acc[nt][0][3] + acc[nt][1][3] + acc[nt][2][3];
            }
        }
        __syncthreads();

        // ---- cell update: thread owns (cell jj, batch bl); 4-way k reduction ----
        {
            float s0 = cb[jj * 4 + 0], s1 = cb[jj * 4 + 1];
            float s2 = cb[jj * 4 + 2], s3 = cb[jj * 4 + 3];
#pragma unroll
            for (int c = 0; c < 4; ++c) {
                const float* g = gsm + c * GSMC;
                s0 += g[(jj * 4 + 0) * 65 + bl];
                s1 += g[(jj * 4 + 1) * 65 + bl];
                s2 += g[(jj * 4 + 2) * 65 + bl];
                s3 += g[(jj * 4 + 3) * 65 + bl];
            }
            if (IS_L0) {
                const float* wr = wih + (size_t)(mb * 8 + jj) * IIN;
#pragma unroll
                for (int k = 0; k < IIN; ++k) {
                    float xv = Xs[bl * IIN + k];
                    s0 = fmaf(__ldg(wr + 0 * HH * IIN + k), xv, s0);
                    s1 = fmaf(__ldg(wr + 1 * HH * IIN + k), xv, s1);
                    s2 = fmaf(__ldg(wr + 2 * HH * IIN + k), xv, s2);
                    s3 = fmaf(__ldg(wr + 3 * HH * IIN + k), xv, s3);
                }
            } else {
                s0 += pr[0]; s1 += pr[1]; s2 += pr[2]; s3 += pr[3];
            }
            cst = sigf(s1) * cst + sigf(s0) * tanhf(s2);
            float h = sigf(s3) * tanhf(cst);
            float2 hs = split_tf32(h);
            hsm_hi[jj * 64 + bl] = hs.x;
            hsm_lo[jj * 64 + bl] = hs.y;
        }
        __syncthreads();

        // ---- publish h (slot t+1), coalesced ----
        {
            float* dst = hbuf + (size_t)(t + 1) * BSLOT;
#pragma unroll
            for (int u = 0; u < 2; ++u) {
                int f = tid + u * NTHR;
                int b = f >> 4, rem = f & 15, p = rem >> 2, q = rem & 3;
                int j = p + (q & 1) * 4;
                float v = (q < 2) ? hsm_hi[j * 64 + b] : hsm_lo[j * 64 + b];
                __stcg(&dst[((size_t)(mb * 128 + b0 + b) << 4) + (p << 2) + q], v);
            }
        }
        __syncthreads();
        if (tid == 0) bar_arrive();
    }
    barrier_epilogue();
}

// ================= proj1 GEMM: proj1[t][m'][b] = wih1' @ y0[t] =================
extern "C" __global__ void __launch_bounds__(256, 1)
proj1_gemm()
{
    const int tid = threadIdx.x;
    const int lane = tid & 31, wid = tid >> 5;
    const int wm = wid & 1, wn = wid >> 1;
    const int gi = lane >> 2, ti = lane & 3;
    const int mc = blockIdx.x & 15;
    const int t  = blockIdx.x >> 4;

    float acc[4][4][4];
#pragma unroll
    for (int a = 0; a < 4; ++a)
#pragma unroll
        for (int b = 0; b < 4; ++b)
#pragma unroll
            for (int c = 0; c < 4; ++c) acc[a][b][c] = 0.f;

    const float4* A4 = (const float4*)g_A1i;
    const float4* B4 = (const float4*)(g_y0b + (size_t)(t + 1) * BSLOT);
    const int mt0 = mc * 8 + wm * 4;

#pragma unroll 2
    for (int kt = 0; kt < 64; ++kt) {
        float4 ah[4], al[4], bv[4];
#pragma unroll
        for (int mt = 0; mt < 4; ++mt) {
            size_t base = ((size_t)((mt0 + mt) * 64 + kt) * 32 + lane) * 2;
            ah[mt] = A4[base];
            al[mt] = A4[base + 1];
        }
#pragma unroll
        for (int nt = 0; nt < 4; ++nt) {
            int bg = wn * 32 + nt * 8 + gi;
            bv[nt] = B4[(size_t)(kt * 128 + bg) * 4 + ti];
        }
#pragma unroll
        for (int mt = 0; mt < 4; ++mt)
#pragma unroll
            for (int nt = 0; nt < 4; ++nt) {
                mma_tf32(acc[mt][nt], ah[mt], bv[nt].x, bv[nt].y);
                mma_tf32(acc[mt][nt], ah[mt], bv[nt].z, bv[nt].w);
                mma_tf32(acc[mt][nt], al[mt], bv[nt].x, bv[nt].y);
            }
    }

#pragma unroll
    for (int mt = 0; mt < 4; ++mt)
#pragma unroll
        for (int nt = 0; nt < 4; ++nt) {
            int r = (mt0 + mt) * 16 + gi;
            int b = wn * 32 + nt * 8 + 2 * ti;
            float* p0 = g_proj1 + ((size_t)t * 2048 + r) * BB + b;
            p0[0] = acc[mt][nt][0];
            p0[1] = acc[mt][nt][1];
            float* p1 = p0 + 8 * BB;
            p1[0] = acc[mt][nt][2];
            p1[1] = acc[mt][nt][3];
        }
}

// ---------------- final linear ----------------
extern "C" __global__ void final_linear(const float* __restrict__ lin_w,
                                        const float* __restrict__ lin_b,
                                        float* __restrict__ out)
{
    __shared__ float wrow[HH];
    int o = blockIdx.x, b = threadIdx.x;
    for (int k = b; k < HH; k += 128) wrow[k] = lin_w[o * HH + k];
    __syncthreads();
    const float* hb = g_h1b + (size_t)TT * BSLOT;
    float acc = 0.f;
#pragma unroll 4
    for (int j = 0; j < HH; ++j) {
        int kt = j >> 3, p = j & 3, s = (j >> 2) & 1;
        size_t base = ((size_t)(kt * 128 + b) << 4) + (p << 2);
        float h = hb[base + s] + hb[base + 2 + s];
        acc = fmaf(h, wrow[j], acc);
    }
    out[b * OOUT + o] = acc + lin_b[o];
}

// ---------------- launch ----------------
extern "C" void kernel_launch(void* const* d_in, const int* in_sizes, int n_in,
                              void* d_out, int out_size)
{
    const float* x     = (const float*)d_in[0];
    const float* wih0  = (const float*)d_in[1];
    const float* whh0  = (const float*)d_in[2];
    const float* bih0  = (const float*)d_in[3];
    const float* bhh0  = (const float*)d_in[4];
    const float* wih1  = (const float*)d_in[5];
    const float* whh1  = (const float*)d_in[6];
    const float* bih1  = (const float*)d_in[7];
    const float* bhh1  = (const float*)d_in[8];
    const float* lin_w = (const float*)d_in[9];
    const float* lin_b = (const float*)d_in[10];

    cudaFuncSetAttribute(lstm_rec<true>,  cudaFuncAttributeMaxDynamicSharedMemorySize, SMEM_BYTES);
    cudaFuncSetAttribute(lstm_rec<false>, cudaFuncAttributeMaxDynamicSharedMemorySize, SMEM_BYTES);

    prep_weights<<<(3 * 2048 * 512 + 255) / 256, 256>>>(whh0, wih1, whh1);
    lstm_rec<true><<<NBLK, NTHR, SMEM_BYTES>>>(x, wih0, bih0, bhh0);
    proj1_gemm<<<16384, 256>>>();
    lstm_rec<false><<<NBLK, NTHR, SMEM_BYTES>>>(nullptr, nullptr, bih1, bhh1);
    final_linear<<<OOUT, 128>>>(lin_w, lin_b, (float*)d_out);
}

// round 8
// speedup vs baseline: 2.7246x; 1.0184x over previous
#include <cuda_runtime.h>
#include <cstdint>

#define BB   128
#define TT   1024
#define HH   512
#define IIN  17
#define OOUT 17
#define NBLK 128
#define NTHR 512

// B'' slot: 64 k-tiles x 128 batch x 16 floats {hi(k),hi(k+4),lo(k),lo(k+4)}
#define BSLOT (64 * 128 * 16)          // 131072 floats = 512KB
// A' matrix: 128 m-tiles x 64 k-tiles x 32 lanes x 8 floats {hi[4], lo[4]}
#define AMAT  (128 * 64 * 32 * 8)      // 8MB

// ---------------- device scratch ----------------
__device__ float g_A0 [AMAT];
__device__ float g_A1i[AMAT];
__device__ float g_A1h[AMAT];
__device__ float g_y0b[(size_t)(TT + 1) * BSLOT];
__device__ float g_h1b[(size_t)(TT + 1) * BSLOT];
__device__ float g_proj1[(size_t)TT * 2048 * BB];

__device__ unsigned          g_cnt[8][32];
__device__ unsigned          g_root = 0;
__device__ volatile unsigned g_sense = 0;
__device__ unsigned          g_done = 0;

// ---------------- split-phase grid barrier (monotonic counters) ----------------
__device__ __forceinline__ void bar_arrive()
{
    __threadfence();
    unsigned gid = blockIdx.x & 7;
    if ((atomicAdd(&g_cnt[gid][0], 1u) & 15u) == 15u) {
        __threadfence();
        if ((atomicAdd(&g_root, 1u) & 7u) == 7u) {
            __threadfence();
            atomicAdd((unsigned*)&g_sense, 1u);
        }
    }
}
__device__ __forceinline__ void bar_wait(unsigned tgt)
{
    while (g_sense < tgt) { }
    __threadfence();
}
__device__ __forceinline__ void barrier_epilogue()
{
    if (threadIdx.x == 0) {
        __threadfence();
        atomicAdd(&g_done, 1u);
        if (blockIdx.x == 0) {
            while (*(volatile unsigned*)&g_done < NBLK) { }
            for (int i = 0; i < 8; ++i) g_cnt[i][0] = 0;
            g_root = 0;
            g_done = 0;
            g_sense = 0;
            __threadfence();
        }
    }
}

// ---------------- tf32 helpers ----------------
__device__ __forceinline__ float2 split_tf32(float w)
{
    uint32_t hb;
    asm("cvt.rna.tf32.f32 %0, %1;" : "=r"(hb) : "f"(w));
    float hi = __uint_as_float(hb);
    float r = w - hi;
    uint32_t lb;
    asm("cvt.rna.tf32.f32 %0, %1;" : "=r"(lb) : "f"(r));
    return make_float2(hi, __uint_as_float(lb));
}

__device__ __forceinline__ void mma_tf32(float c[4], const float4& a,
                                         float b0, float b1)
{
    asm("mma.sync.aligned.m16n8k8.row.col.f32.tf32.tf32.f32 "
        "{%0,%1,%2,%3}, {%4,%5,%6,%7}, {%8,%9}, {%0,%1,%2,%3};"
        : "+f"(c[0]), "+f"(c[1]), "+f"(c[2]), "+f"(c[3])
        : "r"(__float_as_uint(a.x)), "r"(__float_as_uint(a.y)),
          "r"(__float_as_uint(a.z)), "r"(__float_as_uint(a.w)),
          "r"(__float_as_uint(b0)), "r"(__float_as_uint(b1)));
}

__device__ __forceinline__ float sigf(float v) { return 1.f / (1.f + expf(-v)); }

// ---------------- weight prep: split + fragment reorder ----------------
extern "C" __global__ void prep_weights(const float* __restrict__ whh0,
                                        const float* __restrict__ wih1,
                                        const float* __restrict__ whh1)
{
    const int ME = 2048 * 512;
    int idx = blockIdx.x * blockDim.x + threadIdx.x;
    if (idx >= 3 * ME) return;
    int mat = idx / ME, e = idx % ME;
    int mp = e >> 9, k = e & 511;
    int cell = mp >> 2, g = mp & 3;
    const float* W = (mat == 0) ? whh0 : (mat == 1) ? wih1 : whh1;
    float2 s = split_tf32(W[(size_t)(g * HH + cell) * HH + k]);
    int mt = mp >> 4, rl = mp & 15;
    int kt = k >> 3,  cl = k & 7;
    int a = (rl >> 3) | ((cl >> 2) << 1);
    int lane = (rl & 7) * 4 + (cl & 3);
    float* dst = (mat == 0) ? g_A0 : (mat == 1) ? g_A1i : g_A1h;
    size_t base = (((size_t)mt * 64 + kt) * 32 + lane) * 8;
    dst[base + a]     = s.x;
    dst[base + 4 + a] = s.y;
}

// ================= recurrent kernel (both layers) =================
// grid 128 = 64 mb x 2 nb.  Block: 8 cells (32 gate rows) x 64 batches.
// 16 warps: wn(2 n-halves of 32) x wk(8 k-groups of 8 kt).
// Warp tile: m32 (both m-tiles) x n32 (4 n-tiles); merged-term accumulators.
#define GSMC 2080                      // one gsm copy: 32 rows x 65
#define NKC  8                         // k-split copies
#define SMEM_FLOATS (32768 + NKC*GSMC + 2*8*64 + 32 + 64*IIN)
#define SMEM_BYTES  (SMEM_FLOATS * 4)

template<bool IS_L0>
__global__ void __launch_bounds__(NTHR, 1)
lstm_rec(const float* __restrict__ x,
         const float* __restrict__ wih,
         const float* __restrict__ bih, const float* __restrict__ bhh)
{
    extern __shared__ float sm[];
    float*  ahi = sm;                          // 16384
    float*  alo = sm + 16384;                  // 16384
    float*  gsm = sm + 32768;                  // NKC * 2080
    float*  hsm_hi = gsm + NKC * GSMC;         // 8*64
    float*  hsm_lo = hsm_hi + 8 * 64;          // 8*64
    float*  cb  = hsm_lo + 8 * 64;             // 32
    float*  Xs  = cb + 32;                     // 64*17 (L0 only)

    const float* Afrag = IS_L0 ? g_A0 : g_A1h;
    float*       hbuf  = IS_L0 ? g_y0b : g_h1b;

    const int tid = threadIdx.x;
    const int lane = tid & 31, wid = tid >> 5;
    const int wn = wid & 1, wk = wid >> 1;          // 2 n-halves x 8 k-groups
    const int gi = lane >> 2, ti = lane & 3;
    const int mb = blockIdx.x >> 1, nb = blockIdx.x & 1;
    const int b0 = nb * 64;
    const int jj = tid >> 6, bl = tid & 63;         // epilogue: cell jj, batch bl

    // ---- prologue: A slice -> smem (hi/lo de-interleaved) ----
    {
        const float4* src4 = (const float4*)(Afrag + (size_t)mb * 32768);
        float4* ahi4 = (float4*)ahi;
        float4* alo4 = (float4*)alo;
        for (int i = tid; i < 4096; i += NTHR) {
            ahi4[i] = src4[2 * i];
            alo4[i] = src4[2 * i + 1];
        }
    }
    if (tid < 32) {
        int cell = mb * 8 + (tid >> 2), g = tid & 3;
        cb[tid] = bih[g * HH + cell] + bhh[g * HH + cell];
    }
    // zero slot 0 of our tile
    for (int f = tid; f < 1024; f += NTHR) {
        int b = f >> 4, r = f & 15;
        __stcg(&hbuf[((size_t)(mb * 128 + b0 + b) << 4) + r], 0.f);
    }
    __syncthreads();
    if (tid == 0) bar_arrive();                 // round 1: slot-0 published

    float cst = 0.f;
    const float4* ahi4 = (const float4*)ahi;
    const float4* alo4 = (const float4*)alo;

    unsigned tgt = 0;

    for (int t = 0; t < TT; ++t) {
        float pr[4];
        if (IS_L0) {
            for (int idx = tid; idx < 64 * IIN; idx += NTHR) {
                int r = idx / IIN, k = idx - r * IIN;
                Xs[idx] = x[((size_t)(b0 + r) * TT + t) * IIN + k];
            }
        } else {
            const float* pp = g_proj1 + ((size_t)t * 2048 + mb * 32 + jj * 4) * BB + b0 + bl;
#pragma unroll
            for (int g = 0; g < 4; ++g) pr[g] = __ldcg(pp + g * BB);
        }

        ++tgt;
        if (tid == 0) bar_wait(tgt);            // h slot t ready grid-wide
        __syncthreads();

        // ---- mma sweep: 8 kt, m32 x n32, merged 3-term accumulators ----
        float acc[2][4][4];
#pragma unroll
        for (int mt = 0; mt < 2; ++mt)
#pragma unroll
            for (int nt = 0; nt < 4; ++nt)
#pragma unroll
                for (int i = 0; i < 4; ++i) acc[mt][nt][i] = 0.f;

        const float4* Bt = (const float4*)(hbuf + (size_t)t * BSLOT);
#pragma unroll 2
        for (int kt = 0; kt < 8; ++kt) {
            int ktg = wk * 8 + kt;
            float4 ah0 = ahi4[(0 * 64 + ktg) * 32 + lane];
            float4 al0 = alo4[(0 * 64 + ktg) * 32 + lane];
            float4 ah1 = ahi4[(1 * 64 + ktg) * 32 + lane];
            float4 al1 = alo4[(1 * 64 + ktg) * 32 + lane];
#pragma unroll
            for (int nt = 0; nt < 4; ++nt) {
                float4 bv = Bt[(size_t)(ktg * 128 + b0 + wn * 32 + nt * 8 + gi) * 4 + ti];
                mma_tf32(acc[0][nt], ah0, bv.x, bv.y);   // hi*hi
                mma_tf32(acc[0][nt], ah0, bv.z, bv.w);   // hi*lo
                mma_tf32(acc[0][nt], al0, bv.x, bv.y);   // lo*hi
                mma_tf32(acc[1][nt], ah1, bv.x, bv.y);
                mma_tf32(acc[1][nt], ah1, bv.z, bv.w);
                mma_tf32(acc[1][nt], al1, bv.x, bv.y);
            }
        }

        // ---- D -> gsm copy [wk] ----
        {
            float* g = gsm + wk * GSMC;
#pragma unroll
            for (int mt = 0; mt < 2; ++mt) {
                int r0 = mt * 16 + gi;
#pragma unroll
                for (int nt = 0; nt < 4; ++nt) {
                    int col = wn * 32 + nt * 8 + 2 * ti;
                    g[r0 * 65 + col]           = acc[mt][nt][0];
                    g[r0 * 65 + col + 1]       = acc[mt][nt][1];
                    g[(r0 + 8) * 65 + col]     = acc[mt][nt][2];
                    g[(r0 + 8) * 65 + col + 1] = acc[mt][nt][3];
                }
            }
        }
        __syncthreads();

        // ---- cell update: thread owns (cell jj, batch bl); 8-way k reduction ----
        {
            float s0 = cb[jj * 4 + 0], s1 = cb[jj * 4 + 1];
            float s2 = cb[jj * 4 + 2], s3 = cb[jj * 4 + 3];
#pragma unroll
            for (int c = 0; c < NKC; ++c) {
                const float* g = gsm + c * GSMC;
                s0 += g[(jj * 4 + 0) * 65 + bl];
                s1 += g[(jj * 4 + 1) * 65 + bl];
                s2 += g[(jj * 4 + 2) * 65 + bl];
                s3 += g[(jj * 4 + 3) * 65 + bl];
            }
            if (IS_L0) {
                const float* wr = wih + (size_t)(mb * 8 + jj) * IIN;
#pragma unroll
                for (int k = 0; k < IIN; ++k) {
                    float xv = Xs[bl * IIN + k];
                    s0 = fmaf(__ldg(wr + 0 * HH * IIN + k), xv, s0);
                    s1 = fmaf(__ldg(wr + 1 * HH * IIN + k), xv, s1);
                    s2 = fmaf(__ldg(wr + 2 * HH * IIN + k), xv, s2);
                    s3 = fmaf(__ldg(wr + 3 * HH * IIN + k), xv, s3);
                }
            } else {
                s0 += pr[0]; s1 += pr[1]; s2 += pr[2]; s3 += pr[3];
            }
            cst = sigf(s1) * cst + sigf(s0) * tanhf(s2);
            float h = sigf(s3) * tanhf(cst);
            float2 hs = split_tf32(h);
            hsm_hi[jj * 64 + bl] = hs.x;
            hsm_lo[jj * 64 + bl] = hs.y;
        }
        __syncthreads();

        // ---- publish h (slot t+1), coalesced ----
        {
            float* dst = hbuf + (size_t)(t + 1) * BSLOT;
#pragma unroll
            for (int u = 0; u < 2; ++u) {
                int f = tid + u * NTHR;
                int b = f >> 4, rem = f & 15, p = rem >> 2, q = rem & 3;
                int j = p + (q & 1) * 4;
                float v = (q < 2) ? hsm_hi[j * 64 + b] : hsm_lo[j * 64 + b];
                __stcg(&dst[((size_t)(mb * 128 + b0 + b) << 4) + (p << 2) + q], v);
            }
        }
        __syncthreads();
        if (tid == 0) bar_arrive();
    }
    barrier_epilogue();
}

// ================= proj1 GEMM: proj1[t][m'][b] = wih1' @ y0[t] =================
extern "C" __global__ void __launch_bounds__(256, 1)
proj1_gemm()
{
    const int tid = threadIdx.x;
    const int lane = tid & 31, wid = tid >> 5;
    const int wm = wid & 1, wn = wid >> 1;
    const int gi = lane >> 2, ti = lane & 3;
    const int mc = blockIdx.x & 15;
    const int t  = blockIdx.x >> 4;

    float acc[4][4][4];
#pragma unroll
    for (int a = 0; a < 4; ++a)
#pragma unroll
        for (int b = 0; b < 4; ++b)
#pragma unroll
            for (int c = 0; c < 4; ++c) acc[a][b][c] = 0.f;

    const float4* A4 = (const float4*)g_A1i;
    const float4* B4 = (const float4*)(g_y0b + (size_t)(t + 1) * BSLOT);
    const int mt0 = mc * 8 + wm * 4;

#pragma unroll 2
    for (int kt = 0; kt < 64; ++kt) {
        float4 ah[4], al[4], bv[4];
#pragma unroll
        for (int mt = 0; mt < 4; ++mt) {
            size_t base = ((size_t)((mt0 + mt) * 64 + kt) * 32 + lane) * 2;
            ah[mt] = A4[base];
            al[mt] = A4[base + 1];
        }
#pragma unroll
        for (int nt = 0; nt < 4; ++nt) {
            int bg = wn * 32 + nt * 8 + gi;
            bv[nt] = B4[(size_t)(kt * 128 + bg) * 4 + ti];
        }
#pragma unroll
        for (int mt = 0; mt < 4; ++mt)
#pragma unroll
            for (int nt = 0; nt < 4; ++nt) {
                mma_tf32(acc[mt][nt], ah[mt], bv[nt].x, bv[nt].y);
                mma_tf32(acc[mt][nt], ah[mt], bv[nt].z, bv[nt].w);
                mma_tf32(acc[mt][nt], al[mt], bv[nt].x, bv[nt].y);
            }
    }

#pragma unroll
    for (int mt = 0; mt < 4; ++mt)
#pragma unroll
        for (int nt = 0; nt < 4; ++nt) {
            int r = (mt0 + mt) * 16 + gi;
            int b = wn * 32 + nt * 8 + 2 * ti;
            float* p0 = g_proj1 + ((size_t)t * 2048 + r) * BB + b;
            p0[0] = acc[mt][nt][0];
            p0[1] = acc[mt][nt][1];
            float* p1 = p0 + 8 * BB;
            p1[0] = acc[mt][nt][2];
            p1[1] = acc[mt][nt][3];
        }
}

// ---------------- final linear ----------------
extern "C" __global__ void final_linear(const float* __restrict__ lin_w,
                                        const float* __restrict__ lin_b,
                                        float* __restrict__ out)
{
    __shared__ float wrow[HH];
    int o = blockIdx.x, b = threadIdx.x;
    for (int k = b; k < HH; k += 128) wrow[k] = lin_w[o * HH + k];
    __syncthreads();
    const float* hb = g_h1b + (size_t)TT * BSLOT;
    float acc = 0.f;
#pragma unroll 4
    for (int j = 0; j < HH; ++j) {
        int kt = j >> 3, p = j & 3, s = (j >> 2) & 1;
        size_t base = ((size_t)(kt * 128 + b) << 4) + (p << 2);
        float h = hb[base + s] + hb[base + 2 + s];
        acc = fmaf(h, wrow[j], acc);
    }
    out[b * OOUT + o] = acc + lin_b[o];
}

// ---------------- launch ----------------
extern "C" void kernel_launch(void* const* d_in, const int* in_sizes, int n_in,
                              void* d_out, int out_size)
{
    const float* x     = (const float*)d_in[0];
    const float* wih0  = (const float*)d_in[1];
    const float* whh0  = (const float*)d_in[2];
    const float* bih0  = (const float*)d_in[3];
    const float* bhh0  = (const float*)d_in[4];
    const float* wih1  = (const float*)d_in[5];
    const float* whh1  = (const float*)d_in[6];
    const float* bih1  = (const float*)d_in[7];
    const float* bhh1  = (const float*)d_in[8];
    const float* lin_w = (const float*)d_in[9];
    const float* lin_b = (const float*)d_in[10];

    cudaFuncSetAttribute(lstm_rec<true>,  cudaFuncAttributeMaxDynamicSharedMemorySize, SMEM_BYTES);
    cudaFuncSetAttribute(lstm_rec<false>, cudaFuncAttributeMaxDynamicSharedMemorySize, SMEM_BYTES);

    prep_weights<<<(3 * 2048 * 512 + 255) / 256, 256>>>(whh0, wih1, whh1);
    lstm_rec<true><<<NBLK, NTHR, SMEM_BYTES>>>(x, wih0, bih0, bhh0);
    proj1_gemm<<<16384, 256>>>();
    lstm_rec<false><<<NBLK, NTHR, SMEM_BYTES>>>(nullptr, nullptr, bih1, bhh1);
    final_linear<<<OOUT, 128>>>(lin_w, lin_b, (float*)d_out);
}

// round 10
// speedup vs baseline: 3.7540x; 1.3778x over previous
#include <cuda_runtime.h>
#include <cuda_bf16.h>
#include <cstdint>

#define BB   128
#define TT   1024
#define HH   512
#define IIN  17
#define OOUT 17
#define NBLK 128
#define NTHR 512
#define NKT  32                        // k16 tiles over K=512

// B'' slot layout: per (kt, b): 4 float4s indexed by ti, each
// {h1[ti], h1[ti+4], h2[ti], h2[ti+4]} (u32 = bf16 pair, k even low / odd high).
#define BSLOT_U32 (32 * 128 * 16)      // 65536 u32 = 256KB per slot
// A: per (mt, kt, lane): 16 u16 = {hi a0..a3, lo a0..a3}; 128 mt x 32 kt
#define AMAT_U16 (128 * 32 * 32 * 16)  // ushort units, 4MB

typedef unsigned int u32;
typedef unsigned short u16;

// ---------------- device scratch ----------------
__device__ u16 g_A0 [AMAT_U16];
__device__ u16 g_A1i[AMAT_U16];
__device__ u16 g_A1h[AMAT_U16];
__device__ u32 g_y0b[(size_t)(TT + 1) * BSLOT_U32];
__device__ u32 g_h1b[(size_t)(TT + 1) * BSLOT_U32];
__device__ float g_proj1[(size_t)TT * 2048 * BB];

__device__ unsigned          g_cnt[8][32];
__device__ unsigned          g_root = 0;
__device__ volatile unsigned g_sense = 0;
__device__ unsigned          g_done = 0;

// ---------------- split-phase grid barrier (monotonic counters) ----------------
__device__ __forceinline__ void bar_arrive()
{
    __threadfence();
    unsigned gid = blockIdx.x & 7;
    if ((atomicAdd(&g_cnt[gid][0], 1u) & 15u) == 15u) {
        __threadfence();
        if ((atomicAdd(&g_root, 1u) & 7u) == 7u) {
            __threadfence();
            atomicAdd((unsigned*)&g_sense, 1u);
        }
    }
}
__device__ __forceinline__ void bar_wait(unsigned tgt)
{
    while (g_sense < tgt) { }
    __threadfence();
}
__device__ __forceinline__ void barrier_epilogue()
{
    if (threadIdx.x == 0) {
        __threadfence();
        atomicAdd(&g_done, 1u);
        if (blockIdx.x == 0) {
            while (*(volatile unsigned*)&g_done < NBLK) { }
            for (int i = 0; i < 8; ++i) g_cnt[i][0] = 0;
            g_root = 0;
            g_done = 0;
            g_sense = 0;
            __threadfence();
        }
    }
}

// ---------------- bf16 helpers ----------------
__device__ __forceinline__ u16 bf16_bits(float v)
{
    return __bfloat16_as_ushort(__float2bfloat16_rn(v));
}
__device__ __forceinline__ float bf16_val(u16 b)
{
    return __bfloat162float(__ushort_as_bfloat16(b));
}
// split fp32 -> (hi, lo) bf16 bits
__device__ __forceinline__ uint2 split_bf16(float w)
{
    u16 hb = bf16_bits(w);
    float r = w - bf16_val(hb);
    u16 lb = bf16_bits(r);
    return make_uint2(hb, lb);
}

__device__ __forceinline__ void mma_bf16(float c[4], const float4& a,
                                         float b0, float b1)
{
    asm("mma.sync.aligned.m16n8k16.row.col.f32.bf16.bf16.f32 "
        "{%0,%1,%2,%3}, {%4,%5,%6,%7}, {%8,%9}, {%0,%1,%2,%3};"
        : "+f"(c[0]), "+f"(c[1]), "+f"(c[2]), "+f"(c[3])
        : "r"(__float_as_uint(a.x)), "r"(__float_as_uint(a.y)),
          "r"(__float_as_uint(a.z)), "r"(__float_as_uint(a.w)),
          "r"(__float_as_uint(b0)), "r"(__float_as_uint(b1)));
}

__device__ __forceinline__ float sigf(float v) { return 1.f / (1.f + expf(-v)); }

// ---------------- weight prep: bf16 split + m16n8k16 fragment reorder --------
// New row m' = cell*4 + gate; source row = gate*512 + cell.
extern "C" __global__ void prep_weights(const float* __restrict__ whh0,
                                        const float* __restrict__ wih1,
                                        const float* __restrict__ whh1)
{
    const int ME = 2048 * 512;
    int idx = blockIdx.x * blockDim.x + threadIdx.x;
    if (idx >= 3 * ME) return;
    int mat = idx / ME, e = idx % ME;
    int mp = e >> 9, k = e & 511;
    int cell = mp >> 2, g = mp & 3;
    const float* W = (mat == 0) ? whh0 : (mat == 1) ? wih1 : whh1;
    uint2 s = split_bf16(W[(size_t)(g * HH + cell) * HH + k]);

    int mt = mp >> 4, rl = mp & 15;
    int gi = rl & 7, mhalf = rl >> 3;
    int kt = k >> 4, kk = k & 15;
    int ti = (kk & 7) >> 1, khalf = kk >> 3, kbit = kk & 1;
    int areg = mhalf + 2 * khalf;
    int lane = gi * 4 + ti;
    u16* dst = (mat == 0) ? g_A0 : (mat == 1) ? g_A1i : g_A1h;
    size_t base16 = (((size_t)mt * 32 + kt) * 32 + lane) * 16;
    dst[base16 + areg * 2 + kbit]     = (u16)s.x;   // hi
    dst[base16 + 8 + areg * 2 + kbit] = (u16)s.y;   // lo
}

// ================= recurrent kernel (both layers) =================
// grid 128 = 64 mb x 2 nb.  Block: 8 cells (32 gate rows) x 64 batches.
// 16 warps: wn(2 n-halves of 32) x wk(8 k-groups of 4 kt).
#define GSMC 2080
#define NKC  8
// smem bytes: ahi 32K + alo 32K + gsm 8*2080*4 + hsm 2K + cb 128 + Xs 4352
#define SMEM_BYTES (32768 + 32768 + NKC*GSMC*4 + 512*4 + 32*4 + 64*IIN*4)

template<bool IS_L0>
__global__ void __launch_bounds__(NTHR, 1)
lstm_rec(const float* __restrict__ x,
         const float* __restrict__ wih,
         const float* __restrict__ bih, const float* __restrict__ bhh)
{
    extern __shared__ char smc[];
    float4* ahi4 = (float4*)smc;                         // 2048 float4
    float4* alo4 = (float4*)(smc + 32768);               // 2048 float4
    float*  gsm  = (float*)(smc + 65536);                // NKC*2080
    u32*    hsm2 = (u32*)(smc + 65536 + NKC*GSMC*4);     // 8*64
    float*  cb   = (float*)((char*)hsm2 + 2048);         // 32
    float*  Xs   = cb + 32;                              // 64*17

    const u16* Afrag = IS_L0 ? g_A0 : g_A1h;
    u32*       hbuf  = IS_L0 ? g_y0b : g_h1b;

    const int tid = threadIdx.x;
    const int lane = tid & 31, wid = tid >> 5;
    const int wn = wid & 1, wk = wid >> 1;
    const int gi = lane >> 2, ti = lane & 3;
    const int mb = blockIdx.x >> 1, nb = blockIdx.x & 1;
    const int b0 = nb * 64;
    const int jj = tid >> 6, bl = tid & 63;
    const int kt0 = mb >> 1, mpar = mb & 1;

    // publish-thread coords: one STG.32 per thread
    const int pb = tid >> 3, pti = (tid >> 1) & 3, pwh = tid & 1;
    const u32 paddr = ((u32)(kt0 * 128 + b0 + pb) * 4 + pti) * 4 + pwh * 2 + mpar;

    // ---- prologue: A slice -> smem (hi/lo de-interleaved) ----
    {
        // block covers mt in {2mb, 2mb+1}: base u16 = 2mb*32*32*16 = mb*32768
        const float4* src4 = (const float4*)(Afrag + (size_t)mb * 32768);
        for (int i = tid; i < 2048; i += NTHR) {
            ahi4[i] = src4[2 * i];
            alo4[i] = src4[2 * i + 1];
        }
    }
    if (tid < 32) {
        int cell = mb * 8 + (tid >> 2), g = tid & 3;
        cb[tid] = bih[g * HH + cell] + bhh[g * HH + cell];
    }
    // zero our slice of slot 0 (same addresses as publish)
    hbuf[paddr] = 0u;
    __syncthreads();
    if (tid == 0) bar_arrive();                 // round 1: slot-0 published

    float cst = 0.f;
    unsigned tgt = 0;

    for (int t = 0; t < TT; ++t) {
        float pr[4];
        if (IS_L0) {
            for (int idx = tid; idx < 64 * IIN; idx += NTHR) {
                int r = idx / IIN, k = idx - r * IIN;
                Xs[idx] = x[((size_t)(b0 + r) * TT + t) * IIN + k];
            }
        } else {
            const float* pp = g_proj1 + ((size_t)t * 2048 + mb * 32 + jj * 4) * BB + b0 + bl;
#pragma unroll
            for (int g = 0; g < 4; ++g) pr[g] = __ldcg(pp + g * BB);
        }

        ++tgt;
        if (tid == 0) bar_wait(tgt);            // h slot t ready grid-wide
        __syncthreads();

        // ---- mma sweep: 4 kt per warp, m32 x n32, merged 3-term accumulators --
        float acc[2][4][4];
#pragma unroll
        for (int mt = 0; mt < 2; ++mt)
#pragma unroll
            for (int nt = 0; nt < 4; ++nt)
#pragma unroll
                for (int i = 0; i < 4; ++i) acc[mt][nt][i] = 0.f;

        const float4* Bt = (const float4*)(hbuf + (size_t)t * BSLOT_U32);
#pragma unroll
        for (int kt = 0; kt < 4; ++kt) {
            int ktg = wk * 4 + kt;
            float4 ah0 = ahi4[(0 * 32 + ktg) * 32 + lane];
            float4 al0 = alo4[(0 * 32 + ktg) * 32 + lane];
            float4 ah1 = ahi4[(1 * 32 + ktg) * 32 + lane];
            float4 al1 = alo4[(1 * 32 + ktg) * 32 + lane];
#pragma unroll
            for (int nt = 0; nt < 4; ++nt) {
                float4 bv = Bt[(size_t)(ktg * 128 + b0 + wn * 32 + nt * 8 + gi) * 4 + ti];
                mma_bf16(acc[0][nt], ah0, bv.x, bv.y);   // a1*b1
                mma_bf16(acc[0][nt], ah0, bv.z, bv.w);   // a1*b2
                mma_bf16(acc[0][nt], al0, bv.x, bv.y);   // a2*b1
                mma_bf16(acc[1][nt], ah1, bv.x, bv.y);
                mma_bf16(acc[1][nt], ah1, bv.z, bv.w);
                mma_bf16(acc[1][nt], al1, bv.x, bv.y);
            }
        }

        // ---- D -> gsm copy [wk] ----
        {
            float* g = gsm + wk * GSMC;
#pragma unroll
            for (int mt = 0; mt < 2; ++mt) {
                int r0 = mt * 16 + gi;
#pragma unroll
                for (int nt = 0; nt < 4; ++nt) {
                    int col = wn * 32 + nt * 8 + 2 * ti;
                    g[r0 * 65 + col]           = acc[mt][nt][0];
                    g[r0 * 65 + col + 1]       = acc[mt][nt][1];
                    g[(r0 + 8) * 65 + col]     = acc[mt][nt][2];
                    g[(r0 + 8) * 65 + col + 1] = acc[mt][nt][3];
                }
            }
        }
        __syncthreads();

        // ---- cell update: thread owns (cell jj, batch bl); 8-way k reduction --
        {
            float s0 = cb[jj * 4 + 0], s1 = cb[jj * 4 + 1];
            float s2 = cb[jj * 4 + 2], s3 = cb[jj * 4 + 3];
#pragma unroll
            for (int c = 0; c < NKC; ++c) {
                const float* g = gsm + c * GSMC;
                s0 += g[(jj * 4 + 0) * 65 + bl];
                s1 += g[(jj * 4 + 1) * 65 + bl];
                s2 += g[(jj * 4 + 2) * 65 + bl];
                s3 += g[(jj * 4 + 3) * 65 + bl];
            }
            if (IS_L0) {
                const float* wr = wih + (size_t)(mb * 8 + jj) * IIN;
#pragma unroll
                for (int k = 0; k < IIN; ++k) {
                    float xv = Xs[bl * IIN + k];
                    s0 = fmaf(__ldg(wr + 0 * HH * IIN + k), xv, s0);
                    s1 = fmaf(__ldg(wr + 1 * HH * IIN + k), xv, s1);
                    s2 = fmaf(__ldg(wr + 2 * HH * IIN + k), xv, s2);
                    s3 = fmaf(__ldg(wr + 3 * HH * IIN + k), xv, s3);
                }
            } else {
                s0 += pr[0]; s1 += pr[1]; s2 += pr[2]; s3 += pr[3];
            }
            cst = sigf(s1) * cst + sigf(s0) * tanhf(s2);
            float h = sigf(s3) * tanhf(cst);
            uint2 hs = split_bf16(h);
            hsm2[jj * 64 + bl] = hs.x | (hs.y << 16);   // lo16 = h1, hi16 = h2
        }
        __syncthreads();

        // ---- publish h (slot t+1): 1 STG.32 per thread in fragment order ----
        {
            u32 w0 = hsm2[(2 * pti) * 64 + pb];
            u32 w1 = hsm2[(2 * pti + 1) * 64 + pb];
            u32 val = __byte_perm(w0, w1, pwh ? 0x7632 : 0x5410);
            __stcg(&hbuf[(size_t)(t + 1) * BSLOT_U32 + paddr], val);
        }
        __syncthreads();
        if (tid == 0) bar_arrive();
    }
    barrier_epilogue();
}

// ================= proj1 GEMM: proj1[t][m'][b] = wih1' @ y0[t] =================
extern "C" __global__ void __launch_bounds__(256, 1)
proj1_gemm()
{
    const int tid = threadIdx.x;
    const int lane = tid & 31, wid = tid >> 5;
    const int wm = wid & 1, wn = wid >> 1;
    const int gi = lane >> 2, ti = lane & 3;
    const int mc = blockIdx.x & 15;
    const int t  = blockIdx.x >> 4;

    float acc[4][4][4];
#pragma unroll
    for (int a = 0; a < 4; ++a)
#pragma unroll
        for (int b = 0; b < 4; ++b)
#pragma unroll
            for (int c = 0; c < 4; ++c) acc[a][b][c] = 0.f;

    const float4* A4 = (const float4*)g_A1i;
    const float4* B4 = (const float4*)(g_y0b + (size_t)(t + 1) * BSLOT_U32);
    const int mt0 = mc * 8 + wm * 4;

#pragma unroll 2
    for (int kt = 0; kt < NKT; ++kt) {
        float4 ah[4], al[4], bv[4];
#pragma unroll
        for (int mt = 0; mt < 4; ++mt) {
            size_t base = (((size_t)(mt0 + mt) * 32 + kt) * 32 + lane) * 2;
            ah[mt] = A4[base];
            al[mt] = A4[base + 1];
        }
#pragma unroll
        for (int nt = 0; nt < 4; ++nt) {
            int bg = wn * 32 + nt * 8 + gi;
            bv[nt] = B4[(size_t)(kt * 128 + bg) * 4 + ti];
        }
#pragma unroll
        for (int mt = 0; mt < 4; ++mt)
#pragma unroll
            for (int nt = 0; nt < 4; ++nt) {
                mma_bf16(acc[mt][nt], ah[mt], bv[nt].x, bv[nt].y);
                mma_bf16(acc[mt][nt], ah[mt], bv[nt].z, bv[nt].w);
                mma_bf16(acc[mt][nt], al[mt], bv[nt].x, bv[nt].y);
            }
    }

#pragma unroll
    for (int mt = 0; mt < 4; ++mt)
#pragma unroll
        for (int nt = 0; nt < 4; ++nt) {
            int r = (mt0 + mt) * 16 + gi;
            int b = wn * 32 + nt * 8 + 2 * ti;
            float* p0 = g_proj1 + ((size_t)t * 2048 + r) * BB + b;
            p0[0] = acc[mt][nt][0];
            p0[1] = acc[mt][nt][1];
            float* p1 = p0 + 8 * BB;
            p1[0] = acc[mt][nt][2];
            p1[1] = acc[mt][nt][3];
        }
}

// ---------------- final linear ----------------
extern "C" __global__ void final_linear(const float* __restrict__ lin_w,
                                        const float* __restrict__ lin_b,
                                        float* __restrict__ out)
{
    __shared__ float wrow[HH];
    int o = blockIdx.x, b = threadIdx.x;
    for (int k = b; k < HH; k += 128) wrow[k] = lin_w[o * HH + k];
    __syncthreads();
    const u32* hb = g_h1b + (size_t)TT * BSLOT_U32;
    float acc = 0.f;
#pragma unroll 4
    for (int j = 0; j < HH; ++j) {
        int kt = j >> 4, kk = j & 15;
        int ti = (kk & 7) >> 1, khalf = kk >> 3, kbit = kk & 1;
        u32 gbase = ((u32)(kt * 128 + b) * 4 + ti) * 4;
        u32 w1 = hb[gbase + khalf];
        u32 w2 = hb[gbase + 2 + khalf];
        u16 b1 = kbit ? (u16)(w1 >> 16) : (u16)(w1 & 0xffff);
        u16 b2 = kbit ? (u16)(w2 >> 16) : (u16)(w2 & 0xffff);
        float h = bf16_val(b1) + bf16_val(b2);
        acc = fmaf(h, wrow[j], acc);
    }
    out[b * OOUT + o] = acc + lin_b[o];
}

// ---------------- launch ----------------
extern "C" void kernel_launch(void* const* d_in, const int* in_sizes, int n_in,
                              void* d_out, int out_size)
{
    const float* x     = (const float*)d_in[0];
    const float* wih0  = (const float*)d_in[1];
    const float* whh0  = (const float*)d_in[2];
    const float* bih0  = (const float*)d_in[3];
    const float* bhh0  = (const float*)d_in[4];
    const float* wih1  = (const float*)d_in[5];
    const float* whh1  = (const float*)d_in[6];
    const float* bih1  = (const float*)d_in[7];
    const float* bhh1  = (const float*)d_in[8];
    const float* lin_w = (const float*)d_in[9];
    const float* lin_b = (const float*)d_in[10];

    cudaFuncSetAttribute(lstm_rec<true>,  cudaFuncAttributeMaxDynamicSharedMemorySize, SMEM_BYTES);
    cudaFuncSetAttribute(lstm_rec<false>, cudaFuncAttributeMaxDynamicSharedMemorySize, SMEM_BYTES);

    prep_weights<<<(3 * 2048 * 512 + 255) / 256, 256>>>(whh0, wih1, whh1);
    lstm_rec<true><<<NBLK, NTHR, SMEM_BYTES>>>(x, wih0, bih0, bhh0);
    proj1_gemm<<<16384, 256>>>();
    lstm_rec<false><<<NBLK, NTHR, SMEM_BYTES>>>(nullptr, nullptr, bih1, bhh1);
    final_linear<<<OOUT, 128>>>(lin_w, lin_b, (float*)d_out);
}

// round 11
// speedup vs baseline: 5.0741x; 1.3516x over previous
#include <cuda_runtime.h>
#include <cuda_bf16.h>
#include <cstdint>

#define BB   128
#define TT   1024
#define HH   512
#define IIN  17
#define OOUT 17
#define NBLK 128
#define NTHR 512

// B'' slot layout: per (kt, b): 4 float4s indexed by ti, each
// {h1[ti], h1[ti+4], h2[ti], h2[ti+4]} (u32 = bf16 pair, k even low / odd high).
#define BSLOT_U32 (32 * 128 * 16)      // 65536 u32 = 256KB per slot
// A: per (mt, kt, lane): 16 u16 = {hi a0..a3, lo a0..a3}; 128 mt x 32 kt
#define AMAT_U16 (128 * 32 * 32 * 16)  // 4MB

typedef unsigned int u32;
typedef unsigned short u16;

// ---------------- device scratch ----------------
__device__ u16 g_A0 [AMAT_U16];                     // whh0 split, frag order
__device__ u16 g_A1i[AMAT_U16];                     // wih1 split
__device__ u16 g_A1h[AMAT_U16];                     // whh1 split
__device__ u32 g_y0b[(size_t)(TT + 1) * BSLOT_U32]; // layer0 h history
__device__ u32 g_h1b[(size_t)(TT + 1) * BSLOT_U32]; // layer1 h history

__device__ unsigned g_root = 0;                     // flat barrier counter
__device__ unsigned g_done = 0;

// ---------------- flat one-hop grid barrier (monotonic) ----------------
__device__ __forceinline__ void bar_arrive()
{
    __threadfence();
    atomicAdd(&g_root, 1u);
}
__device__ __forceinline__ void bar_wait(unsigned need)
{
    while (*(volatile unsigned*)&g_root < need) { }
    __threadfence();
}
__device__ __forceinline__ void barrier_epilogue()
{
    if (threadIdx.x == 0) {
        __threadfence();
        atomicAdd(&g_done, 1u);
        if (blockIdx.x == 0) {
            while (*(volatile unsigned*)&g_done < NBLK) { }
            g_root = 0;
            g_done = 0;
            __threadfence();
        }
    }
}

// ---------------- bf16 helpers ----------------
__device__ __forceinline__ u16 bf16_bits(float v)
{
    return __bfloat16_as_ushort(__float2bfloat16_rn(v));
}
__device__ __forceinline__ float bf16_val(u16 b)
{
    return __bfloat162float(__ushort_as_bfloat16(b));
}
__device__ __forceinline__ uint2 split_bf16(float w)
{
    u16 hb = bf16_bits(w);
    float r = w - bf16_val(hb);
    u16 lb = bf16_bits(r);
    return make_uint2(hb, lb);
}

__device__ __forceinline__ void mma_bf16(float c[4], const float4& a,
                                         float b0, float b1)
{
    asm("mma.sync.aligned.m16n8k16.row.col.f32.bf16.bf16.f32 "
        "{%0,%1,%2,%3}, {%4,%5,%6,%7}, {%8,%9}, {%0,%1,%2,%3};"
        : "+f"(c[0]), "+f"(c[1]), "+f"(c[2]), "+f"(c[3])
        : "r"(__float_as_uint(a.x)), "r"(__float_as_uint(a.y)),
          "r"(__float_as_uint(a.z)), "r"(__float_as_uint(a.w)),
          "r"(__float_as_uint(b0)), "r"(__float_as_uint(b1)));
}

// fast activations: MUFU-based, rel err ~2^-22 (negligible vs bf16 split noise)
__device__ __forceinline__ float sigf(float v)
{
    return __fdividef(1.f, 1.f + __expf(-v));
}
__device__ __forceinline__ float tanhf_fast(float v)
{
    return 1.f - __fdividef(2.f, __expf(2.f * v) + 1.f);
}

// ---------------- weight prep: bf16 split + m16n8k16 fragment reorder --------
extern "C" __global__ void prep_weights(const float* __restrict__ whh0,
                                        const float* __restrict__ wih1,
                                        const float* __restrict__ whh1)
{
    const int ME = 2048 * 512;
    int idx = blockIdx.x * blockDim.x + threadIdx.x;
    if (idx >= 3 * ME) return;
    int mat = idx / ME, e = idx % ME;
    int mp = e >> 9, k = e & 511;
    int cell = mp >> 2, g = mp & 3;
    const float* W = (mat == 0) ? whh0 : (mat == 1) ? wih1 : whh1;
    uint2 s = split_bf16(W[(size_t)(g * HH + cell) * HH + k]);

    int mt = mp >> 4, rl = mp & 15;
    int gi = rl & 7, mhalf = rl >> 3;
    int kt = k >> 4, kk = k & 15;
    int ti = (kk & 7) >> 1, khalf = kk >> 3, kbit = kk & 1;
    int areg = mhalf + 2 * khalf;
    int lane = gi * 4 + ti;
    u16* dst = (mat == 0) ? g_A0 : (mat == 1) ? g_A1i : g_A1h;
    size_t base16 = (((size_t)mt * 32 + kt) * 32 + lane) * 16;
    dst[base16 + areg * 2 + kbit]     = (u16)s.x;   // hi
    dst[base16 + 8 + areg * 2 + kbit] = (u16)s.y;   // lo
}

// ================= fused 2-layer recurrent kernel =================
// grid 128 = 64 mb x 2 nb.  16 warps: wn(2 n-halves) x wk(8 k-groups of 4 kt).
// Round r: phase L0 = layer0 step r (r<TT); phase L1 = layer1 step r-1 (r>=1).
#define GSMC 2080
#define NKC  8
// smem: a0 64K + a1 64K + gsm NKC*2080*4 + hsm2 2K + cb 256B + Xs 4352B
#define SMEM_BYTES (65536 + 65536 + NKC*GSMC*4 + 2048 + 256 + 64*IIN*4)

__device__ __forceinline__ void store_gsm(float* gsm, float acc[2][4][4],
                                          int wk, int wn, int gi, int ti)
{
    float* g = gsm + wk * GSMC;
#pragma unroll
    for (int mt = 0; mt < 2; ++mt) {
        int r0 = mt * 16 + gi;
#pragma unroll
        for (int nt = 0; nt < 4; ++nt) {
            int col = wn * 32 + nt * 8 + 2 * ti;
            g[r0 * 65 + col]           = acc[mt][nt][0];
            g[r0 * 65 + col + 1]       = acc[mt][nt][1];
            g[(r0 + 8) * 65 + col]     = acc[mt][nt][2];
            g[(r0 + 8) * 65 + col + 1] = acc[mt][nt][3];
        }
    }
}

extern "C" __global__ void __launch_bounds__(NTHR, 1)
lstm_fused(const float* __restrict__ x,
           const float* __restrict__ wih0,
           const float* __restrict__ bih0, const float* __restrict__ bhh0,
           const float* __restrict__ bih1, const float* __restrict__ bhh1)
{
    extern __shared__ char smc[];
    float4* a0hi4 = (float4*)smc;                        // 2048 float4
    float4* a0lo4 = (float4*)(smc + 32768);
    float4* a1hi4 = (float4*)(smc + 65536);
    float4* a1lo4 = (float4*)(smc + 98304);
    float*  gsm   = (float*)(smc + 131072);              // NKC*2080
    u32*    hsm2  = (u32*)(smc + 131072 + NKC*GSMC*4);   // 512
    float*  cb0   = (float*)((char*)hsm2 + 2048);        // 32
    float*  cb1   = cb0 + 32;                            // 32
    float*  Xs    = cb1 + 32;                            // 64*17

    const int tid = threadIdx.x;
    const int lane = tid & 31, wid = tid >> 5;
    const int wn = wid & 1, wk = wid >> 1;
    const int gi = lane >> 2, ti = lane & 3;
    const int mb = blockIdx.x >> 1, nb = blockIdx.x & 1;
    const int b0 = nb * 64;
    const int jj = tid >> 6, bl = tid & 63;
    const int kt0 = mb >> 1, mpar = mb & 1;

    const int pb = tid >> 3, pti = (tid >> 1) & 3, pwh = tid & 1;
    const u32 paddr = ((u32)(kt0 * 128 + b0 + pb) * 4 + pti) * 4 + pwh * 2 + mpar;

    // ---- prologue: A slices -> smem (hi/lo de-interleaved) ----
    {
        const float4* s0 = (const float4*)(g_A0  + (size_t)mb * 32768);
        const float4* s1 = (const float4*)(g_A1h + (size_t)mb * 32768);
        for (int i = tid; i < 2048; i += NTHR) {
            a0hi4[i] = s0[2 * i];
            a0lo4[i] = s0[2 * i + 1];
            a1hi4[i] = s1[2 * i];
            a1lo4[i] = s1[2 * i + 1];
        }
    }
    if (tid < 32) {
        int cell = mb * 8 + (tid >> 2), g = tid & 3;
        cb0[tid] = bih0[g * HH + cell] + bhh0[g * HH + cell];
    } else if (tid < 64) {
        int t2 = tid - 32;
        int cell = mb * 8 + (t2 >> 2), g = t2 & 3;
        cb1[t2] = bih1[g * HH + cell] + bhh1[g * HH + cell];
    }
    // zero slot 0 of both buffers
    __stcg(&g_y0b[paddr], 0u);
    __stcg(&g_h1b[paddr], 0u);
    __syncthreads();
    if (tid == 0) bar_arrive();

    float c0st = 0.f, c1st = 0.f;
    unsigned need = NBLK;
    const float4* A1i4 = (const float4*)(g_A1i + (size_t)mb * 32768);

    for (int r = 0; r <= TT; ++r) {
        // stage x_r (overlaps barrier wait)
        if (r < TT) {
            for (int idx = tid; idx < 64 * IIN; idx += NTHR) {
                int rr = idx / IIN, k = idx - rr * IIN;
                Xs[idx] = x[((size_t)(b0 + rr) * TT + r) * IIN + k];
            }
        }
        if (tid == 0) bar_wait(need);
        __syncthreads();

        // ================= phase L0: layer0 step r =================
        if (r < TT) {
            float acc[2][4][4];
#pragma unroll
            for (int mt = 0; mt < 2; ++mt)
#pragma unroll
                for (int nt = 0; nt < 4; ++nt)
#pragma unroll
                    for (int i = 0; i < 4; ++i) acc[mt][nt][i] = 0.f;

            const float4* Bt = (const float4*)(g_y0b + (size_t)r * BSLOT_U32);
#pragma unroll
            for (int kt = 0; kt < 4; ++kt) {
                int ktg = wk * 4 + kt;
                float4 ah0 = a0hi4[ktg * 32 + lane];
                float4 al0 = a0lo4[ktg * 32 + lane];
                float4 ah1 = a0hi4[(32 + ktg) * 32 + lane];
                float4 al1 = a0lo4[(32 + ktg) * 32 + lane];
#pragma unroll
                for (int nt = 0; nt < 4; ++nt) {
                    float4 bv = Bt[(size_t)(ktg * 128 + b0 + wn * 32 + nt * 8 + gi) * 4 + ti];
                    mma_bf16(acc[0][nt], ah0, bv.x, bv.y);
                    mma_bf16(acc[0][nt], ah0, bv.z, bv.w);
                    mma_bf16(acc[0][nt], al0, bv.x, bv.y);
                    mma_bf16(acc[1][nt], ah1, bv.x, bv.y);
                    mma_bf16(acc[1][nt], ah1, bv.z, bv.w);
                    mma_bf16(acc[1][nt], al1, bv.x, bv.y);
                }
            }
            store_gsm(gsm, acc, wk, wn, gi, ti);
            __syncthreads();

            {   // cell update L0
                float s0 = cb0[jj * 4 + 0], s1 = cb0[jj * 4 + 1];
                float s2 = cb0[jj * 4 + 2], s3 = cb0[jj * 4 + 3];
#pragma unroll
                for (int c = 0; c < NKC; ++c) {
                    const float* g = gsm + c * GSMC;
                    s0 += g[(jj * 4 + 0) * 65 + bl];
                    s1 += g[(jj * 4 + 1) * 65 + bl];
                    s2 += g[(jj * 4 + 2) * 65 + bl];
                    s3 += g[(jj * 4 + 3) * 65 + bl];
                }
                const float* wr = wih0 + (size_t)(mb * 8 + jj) * IIN;
#pragma unroll
                for (int k = 0; k < IIN; ++k) {
                    float xv = Xs[bl * IIN + k];
                    s0 = fmaf(__ldg(wr + 0 * HH * IIN + k), xv, s0);
                    s1 = fmaf(__ldg(wr + 1 * HH * IIN + k), xv, s1);
                    s2 = fmaf(__ldg(wr + 2 * HH * IIN + k), xv, s2);
                    s3 = fmaf(__ldg(wr + 3 * HH * IIN + k), xv, s3);
                }
                c0st = sigf(s1) * c0st + sigf(s0) * tanhf_fast(s2);
                float h = sigf(s3) * tanhf_fast(c0st);
                uint2 hs = split_bf16(h);
                hsm2[jj * 64 + bl] = hs.x | (hs.y << 16);
            }
            __syncthreads();

            {   // publish y0 slot r+1
                u32 w0 = hsm2[(2 * pti) * 64 + pb];
                u32 w1 = hsm2[(2 * pti + 1) * 64 + pb];
                u32 val = __byte_perm(w0, w1, pwh ? 0x7632 : 0x5410);
                __stcg(&g_y0b[(size_t)(r + 1) * BSLOT_U32 + paddr], val);
            }
        }

        // ================= phase L1: layer1 step r-1 =================
        if (r >= 1) {
            float acc[2][4][4];
#pragma unroll
            for (int mt = 0; mt < 2; ++mt)
#pragma unroll
                for (int nt = 0; nt < 4; ++nt)
#pragma unroll
                    for (int i = 0; i < 4; ++i) acc[mt][nt][i] = 0.f;

            // recurrent part: A = whh1 (smem), B = h1 slot r-1
            const float4* Bh = (const float4*)(g_h1b + (size_t)(r - 1) * BSLOT_U32);
#pragma unroll
            for (int kt = 0; kt < 4; ++kt) {
                int ktg = wk * 4 + kt;
                float4 ah0 = a1hi4[ktg * 32 + lane];
                float4 al0 = a1lo4[ktg * 32 + lane];
                float4 ah1 = a1hi4[(32 + ktg) * 32 + lane];
                float4 al1 = a1lo4[(32 + ktg) * 32 + lane];
#pragma unroll
                for (int nt = 0; nt < 4; ++nt) {
                    float4 bv = Bh[(size_t)(ktg * 128 + b0 + wn * 32 + nt * 8 + gi) * 4 + ti];
                    mma_bf16(acc[0][nt], ah0, bv.x, bv.y);
                    mma_bf16(acc[0][nt], ah0, bv.z, bv.w);
                    mma_bf16(acc[0][nt], al0, bv.x, bv.y);
                    mma_bf16(acc[1][nt], ah1, bv.x, bv.y);
                    mma_bf16(acc[1][nt], ah1, bv.z, bv.w);
                    mma_bf16(acc[1][nt], al1, bv.x, bv.y);
                }
            }
            // input part: A = wih1 (global/L2), B = y0 slot r
            const float4* By = (const float4*)(g_y0b + (size_t)r * BSLOT_U32);
#pragma unroll
            for (int kt = 0; kt < 4; ++kt) {
                int ktg = wk * 4 + kt;
                size_t b00 = (size_t)(ktg * 32 + lane) * 2;
                size_t b10 = (size_t)((32 + ktg) * 32 + lane) * 2;
                float4 ah0 = __ldg(&A1i4[b00]);
                float4 al0 = __ldg(&A1i4[b00 + 1]);
                float4 ah1 = __ldg(&A1i4[b10]);
                float4 al1 = __ldg(&A1i4[b10 + 1]);
#pragma unroll
                for (int nt = 0; nt < 4; ++nt) {
                    float4 bv = By[(size_t)(ktg * 128 + b0 + wn * 32 + nt * 8 + gi) * 4 + ti];
                    mma_bf16(acc[0][nt], ah0, bv.x, bv.y);
                    mma_bf16(acc[0][nt], ah0, bv.z, bv.w);
                    mma_bf16(acc[0][nt], al0, bv.x, bv.y);
                    mma_bf16(acc[1][nt], ah1, bv.x, bv.y);
                    mma_bf16(acc[1][nt], ah1, bv.z, bv.w);
                    mma_bf16(acc[1][nt], al1, bv.x, bv.y);
                }
            }
            store_gsm(gsm, acc, wk, wn, gi, ti);
            __syncthreads();

            {   // cell update L1
                float s0 = cb1[jj * 4 + 0], s1 = cb1[jj * 4 + 1];
                float s2 = cb1[jj * 4 + 2], s3 = cb1[jj * 4 + 3];
#pragma unroll
                for (int c = 0; c < NKC; ++c) {
                    const float* g = gsm + c * GSMC;
                    s0 += g[(jj * 4 + 0) * 65 + bl];
                    s1 += g[(jj * 4 + 1) * 65 + bl];
                    s2 += g[(jj * 4 + 2) * 65 + bl];
                    s3 += g[(jj * 4 + 3) * 65 + bl];
                }
                c1st = sigf(s1) * c1st + sigf(s0) * tanhf_fast(s2);
                float h = sigf(s3) * tanhf_fast(c1st);
                uint2 hs = split_bf16(h);
                hsm2[jj * 64 + bl] = hs.x | (hs.y << 16);
            }
            __syncthreads();

            {   // publish h1 slot r
                u32 w0 = hsm2[(2 * pti) * 64 + pb];
                u32 w1 = hsm2[(2 * pti + 1) * 64 + pb];
                u32 val = __byte_perm(w0, w1, pwh ? 0x7632 : 0x5410);
                __stcg(&g_h1b[(size_t)r * BSLOT_U32 + paddr], val);
            }
        }

        __syncthreads();
        if (tid == 0) bar_arrive();
        need += NBLK;
    }
    barrier_epilogue();
}

// ---------------- final linear ----------------
extern "C" __global__ void final_linear(const float* __restrict__ lin_w,
                                        const float* __restrict__ lin_b,
                                        float* __restrict__ out)
{
    __shared__ float wrow[HH];
    int o = blockIdx.x, b = threadIdx.x;
    for (int k = b; k < HH; k += 128) wrow[k] = lin_w[o * HH + k];
    __syncthreads();
    const u32* hb = g_h1b + (size_t)TT * BSLOT_U32;
    float acc = 0.f;
#pragma unroll 4
    for (int j = 0; j < HH; ++j) {
        int kt = j >> 4, kk = j & 15;
        int ti = (kk & 7) >> 1, khalf = kk >> 3, kbit = kk & 1;
        u32 gbase = ((u32)(kt * 128 + b) * 4 + ti) * 4;
        u32 w1 = hb[gbase + khalf];
        u32 w2 = hb[gbase + 2 + khalf];
        u16 b1 = kbit ? (u16)(w1 >> 16) : (u16)(w1 & 0xffff);
        u16 b2 = kbit ? (u16)(w2 >> 16) : (u16)(w2 & 0xffff);
        float h = bf16_val(b1) + bf16_val(b2);
        acc = fmaf(h, wrow[j], acc);
    }
    out[b * OOUT + o] = acc + lin_b[o];
}

// ---------------- launch ----------------
extern "C" void kernel_launch(void* const* d_in, const int* in_sizes, int n_in,
                              void* d_out, int out_size)
{
    const float* x     = (const float*)d_in[0];
    const float* wih0  = (const float*)d_in[1];
    const float* whh0  = (const float*)d_in[2];
    const float* bih0  = (const float*)d_in[3];
    const float* bhh0  = (const float*)d_in[4];
    const float* wih1  = (const float*)d_in[5];
    const float* whh1  = (const float*)d_in[6];
    const float* bih1  = (const float*)d_in[7];
    const float* bhh1  = (const float*)d_in[8];
    const float* lin_w = (const float*)d_in[9];
    const float* lin_b = (const float*)d_in[10];

    cudaFuncSetAttribute(lstm_fused, cudaFuncAttributeMaxDynamicSharedMemorySize, SMEM_BYTES);

    prep_weights<<<(3 * 2048 * 512 + 255) / 256, 256>>>(whh0, wih1, whh1);
    lstm_fused<<<NBLK, NTHR, SMEM_BYTES>>>(x, wih0, bih0, bhh0, bih1, bhh1);
    final_linear<<<OOUT, 128>>>(lin_w, lin_b, (float*)d_out);
}